// round 6
// baseline (speedup 1.0000x reference)
#include <cuda_runtime.h>
#include <cuda_bf16.h>
#include <math.h>
#include <stdlib.h>

// Problem constants (from reference setup_inputs)
#define BB 4
#define SS 2048
#define DD 1024
#define FF 4096
#define EE 8
#define TT (BB*SS)          // 8192 tokens
#define CAP 320             // int(2048/8 * 1.25)
#define FCH 1024            // F chunk per wave
#define NWAVE (FF/FCH)      // 4 waves

// ---------------- scratch (~10.6 MB total; no allocations allowed) ----------------
__device__ float g_h[EE * CAP * FCH];   // hidden activations, one F-chunk  [E, CAP, FCH]
__device__ int   g_eidx[TT];            // chosen expert per token
__device__ int   g_slot[TT];            // queue slot or -1 (dropped)
__device__ int   g_order[EE * CAP];     // token id for (expert, slot)
__device__ int   g_cnt[EE];             // capped per-expert token count
__device__ float g_gsum[EE];            // sum of softmax gates per expert

// ---------------- init: zero per-replay accumulators ----------------
__global__ void init_kernel() {
    if (threadIdx.x < EE) g_gsum[threadIdx.x] = 0.0f;
}

// ---------------- zero the output (dropped tokens stay zero) ----------------
__global__ void zero_out_kernel(float* __restrict__ out) {
    size_t i = (size_t)blockIdx.x * 256 + threadIdx.x;   // one float4 each
    float4* p = (float4*)out;
    p[i] = make_float4(0.f, 0.f, 0.f, 0.f);
}

// ---------------- router: logits, softmax stats, argmax ----------------
// 1 warp per token; named scalars only -> registers, zero local memory.
__global__ void router_kernel(const float* __restrict__ x,
                              const float* __restrict__ wr) {
    __shared__ float sg[EE];
    int tid  = threadIdx.x;
    int warp = tid >> 5;
    int lane = tid & 31;
    if (tid < EE) sg[tid] = 0.0f;
    __syncthreads();

    int t = blockIdx.x * 8 + warp;
    const float* xr = x + (size_t)t * DD;

    float p0=0.f,p1=0.f,p2=0.f,p3=0.f,p4=0.f,p5=0.f,p6=0.f,p7=0.f;
    for (int k = lane; k < DD; k += 32) {
        float xv = xr[k];
        const float4* w4 = (const float4*)(wr + (size_t)k * EE);
        float4 w0 = w4[0], w1 = w4[1];
        p0 = fmaf(xv, w0.x, p0); p1 = fmaf(xv, w0.y, p1);
        p2 = fmaf(xv, w0.z, p2); p3 = fmaf(xv, w0.w, p3);
        p4 = fmaf(xv, w1.x, p4); p5 = fmaf(xv, w1.y, p5);
        p6 = fmaf(xv, w1.z, p6); p7 = fmaf(xv, w1.w, p7);
    }
#pragma unroll
    for (int off = 16; off > 0; off >>= 1) {
        p0 += __shfl_xor_sync(0xFFFFFFFFu, p0, off);
        p1 += __shfl_xor_sync(0xFFFFFFFFu, p1, off);
        p2 += __shfl_xor_sync(0xFFFFFFFFu, p2, off);
        p3 += __shfl_xor_sync(0xFFFFFFFFu, p3, off);
        p4 += __shfl_xor_sync(0xFFFFFFFFu, p4, off);
        p5 += __shfl_xor_sync(0xFFFFFFFFu, p5, off);
        p6 += __shfl_xor_sync(0xFFFFFFFFu, p6, off);
        p7 += __shfl_xor_sync(0xFFFFFFFFu, p7, off);
    }

    if (lane == 0) {
        int best = 0; float bv = p0;
        if (p1 > bv) { bv = p1; best = 1; }
        if (p2 > bv) { bv = p2; best = 2; }
        if (p3 > bv) { bv = p3; best = 3; }
        if (p4 > bv) { bv = p4; best = 4; }
        if (p5 > bv) { bv = p5; best = 5; }
        if (p6 > bv) { bv = p6; best = 6; }
        if (p7 > bv) { bv = p7; best = 7; }
        g_eidx[t] = best;
        float m = bv;
        float e0 = __expf(p0 - m), e1 = __expf(p1 - m), e2 = __expf(p2 - m), e3 = __expf(p3 - m);
        float e4 = __expf(p4 - m), e5 = __expf(p5 - m), e6 = __expf(p6 - m), e7 = __expf(p7 - m);
        float inv = 1.0f / (e0+e1+e2+e3+e4+e5+e6+e7);
        atomicAdd(&sg[0], e0 * inv); atomicAdd(&sg[1], e1 * inv);
        atomicAdd(&sg[2], e2 * inv); atomicAdd(&sg[3], e3 * inv);
        atomicAdd(&sg[4], e4 * inv); atomicAdd(&sg[5], e5 * inv);
        atomicAdd(&sg[6], e6 * inv); atomicAdd(&sg[7], e7 * inv);
    }
    __syncthreads();
    if (tid < EE) atomicAdd(&g_gsum[tid], sg[tid]);
}

// ---------------- scan: stable per-expert positions + order table + loss ----------------
// Single block, 1024 threads, 8 tokens per thread. No dynamically-indexed
// per-thread arrays: the expert-indexed base lives in shared memory.
__global__ void scan_kernel(float* __restrict__ d_out, int out_size) {
    __shared__ int wtot[32][EE];
    __shared__ int totals[EE];
    __shared__ int sbase[1024][EE];     // 32 KB

    int tid  = threadIdx.x;
    int warp = tid >> 5;
    int lane = tid & 31;
    int base = tid * 8;

    int el0 = g_eidx[base+0], el1 = g_eidx[base+1], el2 = g_eidx[base+2], el3 = g_eidx[base+3];
    int el4 = g_eidx[base+4], el5 = g_eidx[base+5], el6 = g_eidx[base+6], el7 = g_eidx[base+7];

    int q1 = (el0==el1);
    int q2 = (el0==el2)+(el1==el2);
    int q3 = (el0==el3)+(el1==el3)+(el2==el3);
    int q4 = (el0==el4)+(el1==el4)+(el2==el4)+(el3==el4);
    int q5 = (el0==el5)+(el1==el5)+(el2==el5)+(el3==el5)+(el4==el5);
    int q6 = (el0==el6)+(el1==el6)+(el2==el6)+(el3==el6)+(el4==el6)+(el5==el6);
    int q7 = (el0==el7)+(el1==el7)+(el2==el7)+(el3==el7)+(el4==el7)+(el5==el7)+(el6==el7);

#pragma unroll
    for (int e = 0; e < EE; e++) {
        int cnt = (el0==e)+(el1==e)+(el2==e)+(el3==e)+(el4==e)+(el5==e)+(el6==e)+(el7==e);
        int s = cnt;
#pragma unroll
        for (int off = 1; off < 32; off <<= 1) {
            int o = __shfl_up_sync(0xFFFFFFFFu, s, off);
            if (lane >= off) s += o;
        }
        sbase[tid][e] = s - cnt;
        if (lane == 31) wtot[warp][e] = s;
    }
    __syncthreads();

    if (warp == 0) {
#pragma unroll
        for (int e = 0; e < EE; e++) {
            int v = wtot[lane][e], s = v;
#pragma unroll
            for (int off = 1; off < 32; off <<= 1) {
                int o = __shfl_up_sync(0xFFFFFFFFu, s, off);
                if (lane >= off) s += o;
            }
            wtot[lane][e] = s - v;
            if (lane == 31) totals[e] = s;
        }
    }
    __syncthreads();

#pragma unroll
    for (int e = 0; e < EE; e++) sbase[tid][e] += wtot[warp][e];
    __syncthreads();

    {
        int g0 = sbase[tid][el0];
        int g1 = sbase[tid][el1] + q1;
        int g2 = sbase[tid][el2] + q2;
        int g3 = sbase[tid][el3] + q3;
        int g4 = sbase[tid][el4] + q4;
        int g5 = sbase[tid][el5] + q5;
        int g6 = sbase[tid][el6] + q6;
        int g7 = sbase[tid][el7] + q7;
        g_slot[base+0] = (g0 < CAP) ? g0 : -1;
        g_slot[base+1] = (g1 < CAP) ? g1 : -1;
        g_slot[base+2] = (g2 < CAP) ? g2 : -1;
        g_slot[base+3] = (g3 < CAP) ? g3 : -1;
        g_slot[base+4] = (g4 < CAP) ? g4 : -1;
        g_slot[base+5] = (g5 < CAP) ? g5 : -1;
        g_slot[base+6] = (g6 < CAP) ? g6 : -1;
        g_slot[base+7] = (g7 < CAP) ? g7 : -1;
        if (g0 < CAP) g_order[el0*CAP + g0] = base+0;
        if (g1 < CAP) g_order[el1*CAP + g1] = base+1;
        if (g2 < CAP) g_order[el2*CAP + g2] = base+2;
        if (g3 < CAP) g_order[el3*CAP + g3] = base+3;
        if (g4 < CAP) g_order[el4*CAP + g4] = base+4;
        if (g5 < CAP) g_order[el5*CAP + g5] = base+5;
        if (g6 < CAP) g_order[el6*CAP + g6] = base+6;
        if (g7 < CAP) g_order[el7*CAP + g7] = base+7;
    }

    if (tid < EE) {
        int c = totals[tid];
        g_cnt[tid] = (c < CAP) ? c : CAP;
    }

    if (tid == 0 && out_size > TT * DD) {
        float loss = 0.0f;
        float invT = 1.0f / (float)TT;
#pragma unroll
        for (int e = 0; e < EE; e++)
            loss += ((float)totals[e] * invT) * (g_gsum[e] * invT);
        d_out[TT * DD] = (float)EE * loss;
    }
}

// ======================= fp32 tiled GEMMs, register-only microkernel ==========
// BM=BN=128, BK=16, 256 threads, 8x8 per thread held in 16 NAMED float4s.
// No local arrays, no address-taken locals -> zero local memory.
#define BM 128
#define BN 128
#define BK 16

#define DECL_ACC \
    float4 c0a=make_float4(0,0,0,0), c0b=make_float4(0,0,0,0); \
    float4 c1a=make_float4(0,0,0,0), c1b=make_float4(0,0,0,0); \
    float4 c2a=make_float4(0,0,0,0), c2b=make_float4(0,0,0,0); \
    float4 c3a=make_float4(0,0,0,0), c3b=make_float4(0,0,0,0); \
    float4 c4a=make_float4(0,0,0,0), c4b=make_float4(0,0,0,0); \
    float4 c5a=make_float4(0,0,0,0), c5b=make_float4(0,0,0,0); \
    float4 c6a=make_float4(0,0,0,0), c6b=make_float4(0,0,0,0); \
    float4 c7a=make_float4(0,0,0,0), c7b=make_float4(0,0,0,0);

#define FMA2(av, ra, rb) \
    ra.x = fmaf(av, bb0.x, ra.x); ra.y = fmaf(av, bb0.y, ra.y); \
    ra.z = fmaf(av, bb0.z, ra.z); ra.w = fmaf(av, bb0.w, ra.w); \
    rb.x = fmaf(av, bb1.x, rb.x); rb.y = fmaf(av, bb1.y, rb.y); \
    rb.z = fmaf(av, bb1.z, rb.z); rb.w = fmaf(av, bb1.w, rb.w);

#define MAINLOOP_BODY \
    _Pragma("unroll") \
    for (int k = 0; k < BK; k++) { \
        float4 aa0 = *(const float4*)&As[k][ty8]; \
        float4 aa1 = *(const float4*)&As[k][ty8 + 4]; \
        float4 bb0 = *(const float4*)&Bs[k][tx8]; \
        float4 bb1 = *(const float4*)&Bs[k][tx8 + 4]; \
        FMA2(aa0.x, c0a, c0b) FMA2(aa0.y, c1a, c1b) \
        FMA2(aa0.z, c2a, c2b) FMA2(aa0.w, c3a, c3b) \
        FMA2(aa1.x, c4a, c4b) FMA2(aa1.y, c5a, c5b) \
        FMA2(aa1.z, c6a, c6b) FMA2(aa1.w, c7a, c7b) \
    }

// ---------------- GEMM1: h_chunk = relu(gather(x) @ w1[:,:,chunk] + b1) ----------
__global__ __launch_bounds__(256)
void gemm1_kernel(const float* __restrict__ x, const float* __restrict__ w1,
                  const float* __restrict__ b1, int chunk) {
    int e  = blockIdx.z;
    int m0 = blockIdx.y * BM;
    int n0 = blockIdx.x * BN;
    const float* Bp   = w1 + (size_t)e * DD * FF + (size_t)chunk * FCH;  // (k,n): +k*FF+n
    const float* bias = b1 + (size_t)e * FF + (size_t)chunk * FCH;
    float* C = g_h + (size_t)e * CAP * FCH;
    int cnt = g_cnt[e];

    __shared__ int   srow[BM];
    __shared__ float As[BK][BM];
    __shared__ float Bs[BK][BN];

    int tid = threadIdx.x;
    if (tid < BM) {
        int m = m0 + tid;
        srow[tid] = (m < cnt) ? g_order[e * CAP + m] : -1;
    }
    __syncthreads();

    int arow = tid >> 1;            // 0..127
    int ak   = (tid & 1) * 8;       // 0 or 8
    int bk   = tid >> 4;            // 0..15
    int bc   = (tid & 15) * 8;      // 0..120
    int ty8  = (tid >> 4) * 8;
    int tx8  = (tid & 15) * 8;
    int gt   = srow[arow];
    const float* xrow = (gt >= 0) ? (x + (size_t)gt * DD) : x;

    DECL_ACC

    for (int k0 = 0; k0 < DD; k0 += BK) {
        float4 va0 = make_float4(0,0,0,0), va1 = make_float4(0,0,0,0);
        if (gt >= 0) {
            va0 = *(const float4*)(xrow + k0 + ak);
            va1 = *(const float4*)(xrow + k0 + ak + 4);
        }
        As[ak+0][arow] = va0.x; As[ak+1][arow] = va0.y;
        As[ak+2][arow] = va0.z; As[ak+3][arow] = va0.w;
        As[ak+4][arow] = va1.x; As[ak+5][arow] = va1.y;
        As[ak+6][arow] = va1.z; As[ak+7][arow] = va1.w;

        const float* bp = Bp + (size_t)(k0 + bk) * FF + n0 + bc;
        float4 vb0 = *(const float4*)(bp);
        float4 vb1 = *(const float4*)(bp + 4);
        *(float4*)&Bs[bk][bc]     = vb0;
        *(float4*)&Bs[bk][bc + 4] = vb1;
        __syncthreads();

        MAINLOOP_BODY
        __syncthreads();
    }

    float4 bv0 = *(const float4*)(bias + n0 + tx8);
    float4 bv1 = *(const float4*)(bias + n0 + tx8 + 4);

#define EPI1(i, ra, rb) { int row = m0 + ty8 + i; if (row < CAP) { \
        float4 o0, o1; \
        o0.x = fmaxf(ra.x + bv0.x, 0.f); o0.y = fmaxf(ra.y + bv0.y, 0.f); \
        o0.z = fmaxf(ra.z + bv0.z, 0.f); o0.w = fmaxf(ra.w + bv0.w, 0.f); \
        o1.x = fmaxf(rb.x + bv1.x, 0.f); o1.y = fmaxf(rb.y + bv1.y, 0.f); \
        o1.z = fmaxf(rb.z + bv1.z, 0.f); o1.w = fmaxf(rb.w + bv1.w, 0.f); \
        float4* cp = (float4*)(C + (size_t)row * FCH + n0 + tx8); \
        cp[0] = o0; cp[1] = o1; } }
    EPI1(0, c0a, c0b) EPI1(1, c1a, c1b) EPI1(2, c2a, c2b) EPI1(3, c3a, c3b)
    EPI1(4, c4a, c4b) EPI1(5, c5a, c5b) EPI1(6, c6a, c6b) EPI1(7, c7a, c7b)
#undef EPI1
}

// ---------------- GEMM2: out[token] (+)= h_chunk @ w2[chunk] (+ b2 on wave 0) ----
__global__ __launch_bounds__(256)
void gemm2_kernel(const float* __restrict__ w2, const float* __restrict__ b2,
                  float* __restrict__ out, int chunk, int accflag) {
    int e  = blockIdx.z;
    int m0 = blockIdx.y * BM;
    int n0 = blockIdx.x * BN;
    const float* Ap   = g_h + (size_t)e * CAP * FCH;                        // (m,k): +m*FCH+k
    const float* Bp   = w2 + (size_t)e * FF * DD + (size_t)chunk * FCH * DD; // (k,n): +k*DD+n
    const float* bias = b2 + (size_t)e * DD;
    int cnt = g_cnt[e];

    __shared__ int   srow[BM];
    __shared__ float As[BK][BM];
    __shared__ float Bs[BK][BN];

    int tid = threadIdx.x;
    if (tid < BM) {
        int m = m0 + tid;
        srow[tid] = (m < cnt) ? g_order[e * CAP + m] : -1;
    }
    __syncthreads();

    int arow = tid >> 1;
    int ak   = (tid & 1) * 8;
    int bk   = tid >> 4;
    int bc   = (tid & 15) * 8;
    int ty8  = (tid >> 4) * 8;
    int tx8  = (tid & 15) * 8;
    int grow = m0 + arow;
    const float* arp = Ap + (size_t)((grow < CAP) ? grow : 0) * FCH;
    int avalid = (grow < CAP);

    DECL_ACC

    for (int k0 = 0; k0 < FCH; k0 += BK) {
        float4 va0 = make_float4(0,0,0,0), va1 = make_float4(0,0,0,0);
        if (avalid) {
            va0 = *(const float4*)(arp + k0 + ak);
            va1 = *(const float4*)(arp + k0 + ak + 4);
        }
        As[ak+0][arow] = va0.x; As[ak+1][arow] = va0.y;
        As[ak+2][arow] = va0.z; As[ak+3][arow] = va0.w;
        As[ak+4][arow] = va1.x; As[ak+5][arow] = va1.y;
        As[ak+6][arow] = va1.z; As[ak+7][arow] = va1.w;

        const float* bp = Bp + (size_t)(k0 + bk) * DD + n0 + bc;
        float4 vb0 = *(const float4*)(bp);
        float4 vb1 = *(const float4*)(bp + 4);
        *(float4*)&Bs[bk][bc]     = vb0;
        *(float4*)&Bs[bk][bc + 4] = vb1;
        __syncthreads();

        MAINLOOP_BODY
        __syncthreads();
    }

    float4 bv0 = *(const float4*)(bias + n0 + tx8);
    float4 bv1 = *(const float4*)(bias + n0 + tx8 + 4);

#define EPI2(i, ra, rb) { int lr = ty8 + i; int t = srow[lr]; if (t >= 0) { \
        float4* cp = (float4*)(out + (size_t)t * DD + n0 + tx8); \
        float4 o0, o1; \
        if (accflag) { o0 = cp[0]; o1 = cp[1]; \
            o0.x += ra.x; o0.y += ra.y; o0.z += ra.z; o0.w += ra.w; \
            o1.x += rb.x; o1.y += rb.y; o1.z += rb.z; o1.w += rb.w; \
        } else { \
            o0.x = ra.x + bv0.x; o0.y = ra.y + bv0.y; \
            o0.z = ra.z + bv0.z; o0.w = ra.w + bv0.w; \
            o1.x = rb.x + bv1.x; o1.y = rb.y + bv1.y; \
            o1.z = rb.z + bv1.z; o1.w = rb.w + bv1.w; } \
        cp[0] = o0; cp[1] = o1; } }
    EPI2(0, c0a, c0b) EPI2(1, c1a, c1b) EPI2(2, c2a, c2b) EPI2(3, c3a, c3b)
    EPI2(4, c4a, c4b) EPI2(5, c5a, c5b) EPI2(6, c6a, c6b) EPI2(7, c7a, c7b)
#undef EPI2
}

// ---------------- eager-load insurance (default-priority ctor only) ----------------
// setenv runs as the FIRST statement of this default-priority constructor,
// before any CUDA call in the process (harness touches CUDA only in main).
namespace {
struct ModulePreloader {
    ModulePreloader() {
        setenv("CUDA_MODULE_LOADING", "EAGER", 1);
        void* p = nullptr;
        (void)cudaGetSymbolAddress(&p, g_h);
        (void)cudaGetSymbolAddress(&p, g_eidx);
        (void)cudaGetSymbolAddress(&p, g_slot);
        (void)cudaGetSymbolAddress(&p, g_order);
        (void)cudaGetSymbolAddress(&p, g_cnt);
        (void)cudaGetSymbolAddress(&p, g_gsum);
        cudaFuncAttributes a;
        (void)cudaFuncGetAttributes(&a, (const void*)router_kernel);
        (void)cudaFuncGetAttributes(&a, (const void*)scan_kernel);
        (void)cudaFuncGetAttributes(&a, (const void*)gemm1_kernel);
        (void)cudaFuncGetAttributes(&a, (const void*)gemm2_kernel);
        (void)cudaFuncGetAttributes(&a, (const void*)zero_out_kernel);
        (void)cudaFuncGetAttributes(&a, (const void*)init_kernel);
    }
};
ModulePreloader g_module_preloader;
}

// ---------------- launch ----------------
extern "C" void kernel_launch(void* const* d_in, const int* in_sizes, int n_in,
                              void* d_out, int out_size) {
    const float* x   = (const float*)d_in[0];  // [B,S,D]
    const float* wr  = (const float*)d_in[1];  // [D,E]
    const float* w1  = (const float*)d_in[2];  // [E,D,F]
    const float* b1  = (const float*)d_in[3];  // [E,F]
    const float* w2  = (const float*)d_in[4];  // [E,F,D]
    const float* b2  = (const float*)d_in[5];  // [E,D]
    float* out = (float*)d_out;

    init_kernel<<<1, 32>>>();
    router_kernel<<<TT / 8, 256>>>(x, wr);
    zero_out_kernel<<<(TT * DD / 4) / 256, 256>>>(out);
    scan_kernel<<<1, 1024>>>(out, out_size);

    dim3 grid1(FCH / BN, (CAP + BM - 1) / BM, EE);   // 8 x 3 x 8
    dim3 grid2(DD  / BN, (CAP + BM - 1) / BM, EE);   // 8 x 3 x 8
    for (int c = 0; c < NWAVE; c++) {
        gemm1_kernel<<<grid1, 256>>>(x, w1, b1, c);
        gemm2_kernel<<<grid2, 256>>>(w2, b2, out, c, c > 0 ? 1 : 0);
    }
}

// round 9
// speedup vs baseline: 1.8306x; 1.8306x over previous
#include <cuda_runtime.h>
#include <cuda_bf16.h>
#include <math.h>
#include <stdlib.h>

// Problem constants (from reference setup_inputs)
#define BB 4
#define SS 2048
#define DD 1024
#define FF 4096
#define EE 8
#define TT (BB*SS)          // 8192 tokens
#define CAP 320             // int(2048/8 * 1.25)
#define FCH 1024            // F chunk per wave
#define NWAVE (FF/FCH)      // 4 waves

// ---------------- scratch (~10.6 MB total; no allocations allowed) ----------------
__device__ float g_h[EE * CAP * FCH];   // hidden activations, one F-chunk  [E, CAP, FCH]
__device__ int   g_eidx[TT];            // chosen expert per token
__device__ int   g_slot[TT];            // queue slot or -1 (dropped)
__device__ int   g_order[EE * CAP];     // token id for (expert, slot)
__device__ int   g_cnt[EE];             // capped per-expert token count
__device__ float g_gsum[EE];            // sum of softmax gates per expert

// ---------------- init: zero per-replay accumulators ----------------
__global__ void init_kernel() {
    if (threadIdx.x < EE) g_gsum[threadIdx.x] = 0.0f;
}

// ---------------- zero the output (dropped tokens stay zero) ----------------
__global__ void zero_out_kernel(float* __restrict__ out) {
    size_t i = (size_t)blockIdx.x * 256 + threadIdx.x;   // one float4 each
    float4* p = (float4*)out;
    p[i] = make_float4(0.f, 0.f, 0.f, 0.f);
}

// ---------------- router: logits, softmax stats, argmax ----------------
__global__ void router_kernel(const float* __restrict__ x,
                              const float* __restrict__ wr) {
    __shared__ float sg[EE];
    int tid  = threadIdx.x;
    int warp = tid >> 5;
    int lane = tid & 31;
    if (tid < EE) sg[tid] = 0.0f;
    __syncthreads();

    int t = blockIdx.x * 8 + warp;
    const float* xr = x + (size_t)t * DD;

    float p0=0.f,p1=0.f,p2=0.f,p3=0.f,p4=0.f,p5=0.f,p6=0.f,p7=0.f;
    for (int k = lane; k < DD; k += 32) {
        float xv = xr[k];
        const float4* w4 = (const float4*)(wr + (size_t)k * EE);
        float4 w0 = w4[0], w1 = w4[1];
        p0 = fmaf(xv, w0.x, p0); p1 = fmaf(xv, w0.y, p1);
        p2 = fmaf(xv, w0.z, p2); p3 = fmaf(xv, w0.w, p3);
        p4 = fmaf(xv, w1.x, p4); p5 = fmaf(xv, w1.y, p5);
        p6 = fmaf(xv, w1.z, p6); p7 = fmaf(xv, w1.w, p7);
    }
#pragma unroll
    for (int off = 16; off > 0; off >>= 1) {
        p0 += __shfl_xor_sync(0xFFFFFFFFu, p0, off);
        p1 += __shfl_xor_sync(0xFFFFFFFFu, p1, off);
        p2 += __shfl_xor_sync(0xFFFFFFFFu, p2, off);
        p3 += __shfl_xor_sync(0xFFFFFFFFu, p3, off);
        p4 += __shfl_xor_sync(0xFFFFFFFFu, p4, off);
        p5 += __shfl_xor_sync(0xFFFFFFFFu, p5, off);
        p6 += __shfl_xor_sync(0xFFFFFFFFu, p6, off);
        p7 += __shfl_xor_sync(0xFFFFFFFFu, p7, off);
    }

    if (lane == 0) {
        int best = 0; float bv = p0;
        if (p1 > bv) { bv = p1; best = 1; }
        if (p2 > bv) { bv = p2; best = 2; }
        if (p3 > bv) { bv = p3; best = 3; }
        if (p4 > bv) { bv = p4; best = 4; }
        if (p5 > bv) { bv = p5; best = 5; }
        if (p6 > bv) { bv = p6; best = 6; }
        if (p7 > bv) { bv = p7; best = 7; }
        g_eidx[t] = best;
        float m = bv;
        float e0 = __expf(p0 - m), e1 = __expf(p1 - m), e2 = __expf(p2 - m), e3 = __expf(p3 - m);
        float e4 = __expf(p4 - m), e5 = __expf(p5 - m), e6 = __expf(p6 - m), e7 = __expf(p7 - m);
        float inv = 1.0f / (e0+e1+e2+e3+e4+e5+e6+e7);
        atomicAdd(&sg[0], e0 * inv); atomicAdd(&sg[1], e1 * inv);
        atomicAdd(&sg[2], e2 * inv); atomicAdd(&sg[3], e3 * inv);
        atomicAdd(&sg[4], e4 * inv); atomicAdd(&sg[5], e5 * inv);
        atomicAdd(&sg[6], e6 * inv); atomicAdd(&sg[7], e7 * inv);
    }
    __syncthreads();
    if (tid < EE) atomicAdd(&g_gsum[tid], sg[tid]);
}

// ---------------- scan: stable per-expert positions + order table + loss ----------------
__global__ void scan_kernel(float* __restrict__ d_out, int out_size) {
    __shared__ int wtot[32][EE];
    __shared__ int totals[EE];
    __shared__ int sbase[1024][EE];     // 32 KB

    int tid  = threadIdx.x;
    int warp = tid >> 5;
    int lane = tid & 31;
    int base = tid * 8;

    int el0 = g_eidx[base+0], el1 = g_eidx[base+1], el2 = g_eidx[base+2], el3 = g_eidx[base+3];
    int el4 = g_eidx[base+4], el5 = g_eidx[base+5], el6 = g_eidx[base+6], el7 = g_eidx[base+7];

    int q1 = (el0==el1);
    int q2 = (el0==el2)+(el1==el2);
    int q3 = (el0==el3)+(el1==el3)+(el2==el3);
    int q4 = (el0==el4)+(el1==el4)+(el2==el4)+(el3==el4);
    int q5 = (el0==el5)+(el1==el5)+(el2==el5)+(el3==el5)+(el4==el5);
    int q6 = (el0==el6)+(el1==el6)+(el2==el6)+(el3==el6)+(el4==el6)+(el5==el6);
    int q7 = (el0==el7)+(el1==el7)+(el2==el7)+(el3==el7)+(el4==el7)+(el5==el7)+(el6==el7);

#pragma unroll
    for (int e = 0; e < EE; e++) {
        int cnt = (el0==e)+(el1==e)+(el2==e)+(el3==e)+(el4==e)+(el5==e)+(el6==e)+(el7==e);
        int s = cnt;
#pragma unroll
        for (int off = 1; off < 32; off <<= 1) {
            int o = __shfl_up_sync(0xFFFFFFFFu, s, off);
            if (lane >= off) s += o;
        }
        sbase[tid][e] = s - cnt;
        if (lane == 31) wtot[warp][e] = s;
    }
    __syncthreads();

    if (warp == 0) {
#pragma unroll
        for (int e = 0; e < EE; e++) {
            int v = wtot[lane][e], s = v;
#pragma unroll
            for (int off = 1; off < 32; off <<= 1) {
                int o = __shfl_up_sync(0xFFFFFFFFu, s, off);
                if (lane >= off) s += o;
            }
            wtot[lane][e] = s - v;
            if (lane == 31) totals[e] = s;
        }
    }
    __syncthreads();

#pragma unroll
    for (int e = 0; e < EE; e++) sbase[tid][e] += wtot[warp][e];
    __syncthreads();

    {
        int g0 = sbase[tid][el0];
        int g1 = sbase[tid][el1] + q1;
        int g2 = sbase[tid][el2] + q2;
        int g3 = sbase[tid][el3] + q3;
        int g4 = sbase[tid][el4] + q4;
        int g5 = sbase[tid][el5] + q5;
        int g6 = sbase[tid][el6] + q6;
        int g7 = sbase[tid][el7] + q7;
        g_slot[base+0] = (g0 < CAP) ? g0 : -1;
        g_slot[base+1] = (g1 < CAP) ? g1 : -1;
        g_slot[base+2] = (g2 < CAP) ? g2 : -1;
        g_slot[base+3] = (g3 < CAP) ? g3 : -1;
        g_slot[base+4] = (g4 < CAP) ? g4 : -1;
        g_slot[base+5] = (g5 < CAP) ? g5 : -1;
        g_slot[base+6] = (g6 < CAP) ? g6 : -1;
        g_slot[base+7] = (g7 < CAP) ? g7 : -1;
        if (g0 < CAP) g_order[el0*CAP + g0] = base+0;
        if (g1 < CAP) g_order[el1*CAP + g1] = base+1;
        if (g2 < CAP) g_order[el2*CAP + g2] = base+2;
        if (g3 < CAP) g_order[el3*CAP + g3] = base+3;
        if (g4 < CAP) g_order[el4*CAP + g4] = base+4;
        if (g5 < CAP) g_order[el5*CAP + g5] = base+5;
        if (g6 < CAP) g_order[el6*CAP + g6] = base+6;
        if (g7 < CAP) g_order[el7*CAP + g7] = base+7;
    }

    if (tid < EE) {
        int c = totals[tid];
        g_cnt[tid] = (c < CAP) ? c : CAP;
    }

    if (tid == 0 && out_size > TT * DD) {
        float loss = 0.0f;
        float invT = 1.0f / (float)TT;
#pragma unroll
        for (int e = 0; e < EE; e++)
            loss += ((float)totals[e] * invT) * (g_gsum[e] * invT);
        d_out[TT * DD] = (float)EE * loss;
    }
}

// =================== tf32 tensor-core GEMMs (mma.sync.m16n8k8) ===================
// BM=128, BN=64, BK=16, 256 threads = 8 warps (4 m x 2 n), warp tile 32x32.
// Inputs rounded to tf32 with cvt.rna at SMEM-store time; fp32 accumulate.
#define BM 128
#define BN 64
#define BK 16
#define APAD 4
#define BPAD 4

__device__ __forceinline__ unsigned f2tf(float f) {
    unsigned r;
    asm("cvt.rna.tf32.f32 %0, %1;" : "=r"(r) : "f"(f));
    return r;
}

#define MMA_TF32(d, av, bv) \
    asm volatile("mma.sync.aligned.m16n8k8.row.col.f32.tf32.tf32.f32 " \
                 "{%0,%1,%2,%3}, {%4,%5,%6,%7}, {%8,%9}, {%0,%1,%2,%3};" \
                 : "+f"(d[0]), "+f"(d[1]), "+f"(d[2]), "+f"(d[3]) \
                 : "r"(av[0]), "r"(av[1]), "r"(av[2]), "r"(av[3]), \
                   "r"(bv[0]), "r"(bv[1]))

// Shared mainloop macro: fills frags from As/Bs and issues 16 MMAs per BK-iter.
#define TC_MAINLOOP \
    _Pragma("unroll") \
    for (int ks = 0; ks < 2; ks++) { \
        unsigned af[2][4]; \
        _Pragma("unroll") \
        for (int mi = 0; mi < 2; mi++) { \
            int r0 = mwb + mi * 16 + gid; \
            af[mi][0] = __float_as_uint(As[ks*8 + tg    ][r0]); \
            af[mi][1] = __float_as_uint(As[ks*8 + tg    ][r0 + 8]); \
            af[mi][2] = __float_as_uint(As[ks*8 + tg + 4][r0]); \
            af[mi][3] = __float_as_uint(As[ks*8 + tg + 4][r0 + 8]); \
        } \
        unsigned bf[4][2]; \
        _Pragma("unroll") \
        for (int ni = 0; ni < 4; ni++) { \
            int c0 = nwb + ni * 8 + gid; \
            bf[ni][0] = __float_as_uint(Bs[ks*8 + tg    ][c0]); \
            bf[ni][1] = __float_as_uint(Bs[ks*8 + tg + 4][c0]); \
        } \
        _Pragma("unroll") \
        for (int mi = 0; mi < 2; mi++) \
            _Pragma("unroll") \
            for (int ni = 0; ni < 4; ni++) \
                MMA_TF32(acc[mi][ni], af[mi], bf[ni]); \
    }

// ---------------- GEMM1: h_chunk = relu(gather(x) @ w1[:,:,chunk] + b1) ----------
__global__ __launch_bounds__(256)
void gemm1_kernel(const float* __restrict__ x, const float* __restrict__ w1,
                  const float* __restrict__ b1, int chunk) {
    int e  = blockIdx.z;
    int m0 = blockIdx.y * BM;
    int n0 = blockIdx.x * BN;
    const float* Bp   = w1 + (size_t)e * DD * FF + (size_t)chunk * FCH;  // row k stride FF
    const float* bias = b1 + (size_t)e * FF + (size_t)chunk * FCH;
    float* C = g_h + (size_t)e * CAP * FCH;
    int cnt = g_cnt[e];

    __shared__ int   srow[BM];
    __shared__ float As[BK][BM + APAD];
    __shared__ float Bs[BK][BN + BPAD];

    int tid = threadIdx.x;
    if (tid < BM) {
        int m = m0 + tid;
        srow[tid] = (m < cnt) ? g_order[e * CAP + m] : -1;
    }
    __syncthreads();

    int wid = tid >> 5, lane = tid & 31;
    int gid = lane >> 2, tg = lane & 3;
    int mwb = (wid >> 1) * 32;          // warp m offset in tile
    int nwb = (wid & 1) * 32;           // warp n offset in tile

    int arow = tid >> 1;                // 0..127
    int ak   = (tid & 1) * 8;           // 0 or 8
    int bk   = tid >> 4;                // 0..15
    int bc   = (tid & 15) * 4;          // 0..60
    int gt   = srow[arow];
    const float* xrow = (gt >= 0) ? (x + (size_t)gt * DD) : x;

    float acc[2][4][4];
#pragma unroll
    for (int mi = 0; mi < 2; mi++)
#pragma unroll
        for (int ni = 0; ni < 4; ni++)
#pragma unroll
            for (int i = 0; i < 4; i++) acc[mi][ni][i] = 0.0f;

    for (int k0 = 0; k0 < DD; k0 += BK) {
        float4 va0 = make_float4(0,0,0,0), va1 = make_float4(0,0,0,0);
        if (gt >= 0) {
            va0 = *(const float4*)(xrow + k0 + ak);
            va1 = *(const float4*)(xrow + k0 + ak + 4);
        }
        As[ak+0][arow] = __uint_as_float(f2tf(va0.x));
        As[ak+1][arow] = __uint_as_float(f2tf(va0.y));
        As[ak+2][arow] = __uint_as_float(f2tf(va0.z));
        As[ak+3][arow] = __uint_as_float(f2tf(va0.w));
        As[ak+4][arow] = __uint_as_float(f2tf(va1.x));
        As[ak+5][arow] = __uint_as_float(f2tf(va1.y));
        As[ak+6][arow] = __uint_as_float(f2tf(va1.z));
        As[ak+7][arow] = __uint_as_float(f2tf(va1.w));

        float4 vb = *(const float4*)(Bp + (size_t)(k0 + bk) * FF + n0 + bc);
        Bs[bk][bc+0] = __uint_as_float(f2tf(vb.x));
        Bs[bk][bc+1] = __uint_as_float(f2tf(vb.y));
        Bs[bk][bc+2] = __uint_as_float(f2tf(vb.z));
        Bs[bk][bc+3] = __uint_as_float(f2tf(vb.w));
        __syncthreads();

        TC_MAINLOOP
        __syncthreads();
    }

    // epilogue: + bias, relu -> g_h
#pragma unroll
    for (int mi = 0; mi < 2; mi++) {
#pragma unroll
        for (int i = 0; i < 2; i++) {
            int row = m0 + mwb + mi * 16 + gid + i * 8;
            if (row < CAP) {
#pragma unroll
                for (int ni = 0; ni < 4; ni++) {
                    int col = n0 + nwb + ni * 8 + tg * 2;
                    float v0 = fmaxf(acc[mi][ni][i*2+0] + bias[col],     0.0f);
                    float v1 = fmaxf(acc[mi][ni][i*2+1] + bias[col + 1], 0.0f);
                    float2 o; o.x = v0; o.y = v1;
                    *(float2*)(C + (size_t)row * FCH + col) = o;
                }
            }
        }
    }
}

// ---------------- GEMM2: out[token] (+)= h_chunk @ w2[chunk] (+ b2 on wave 0) ----
__global__ __launch_bounds__(256)
void gemm2_kernel(const float* __restrict__ w2, const float* __restrict__ b2,
                  float* __restrict__ out, int chunk, int accflag) {
    int e  = blockIdx.z;
    int m0 = blockIdx.y * BM;
    int n0 = blockIdx.x * BN;
    const float* Ap   = g_h + (size_t)e * CAP * FCH;                         // row m stride FCH
    const float* Bp   = w2 + (size_t)e * FF * DD + (size_t)chunk * FCH * DD; // row k stride DD
    const float* bias = b2 + (size_t)e * DD;
    int cnt = g_cnt[e];

    __shared__ int   srow[BM];
    __shared__ float As[BK][BM + APAD];
    __shared__ float Bs[BK][BN + BPAD];

    int tid = threadIdx.x;
    if (tid < BM) {
        int m = m0 + tid;
        srow[tid] = (m < cnt) ? g_order[e * CAP + m] : -1;
    }
    __syncthreads();

    int wid = tid >> 5, lane = tid & 31;
    int gid = lane >> 2, tg = lane & 3;
    int mwb = (wid >> 1) * 32;
    int nwb = (wid & 1) * 32;

    int arow = tid >> 1;
    int ak   = (tid & 1) * 8;
    int bk   = tid >> 4;
    int bc   = (tid & 15) * 4;
    int grow = m0 + arow;
    const float* arp = Ap + (size_t)((grow < CAP) ? grow : 0) * FCH;
    int avalid = (grow < CAP);

    float acc[2][4][4];
#pragma unroll
    for (int mi = 0; mi < 2; mi++)
#pragma unroll
        for (int ni = 0; ni < 4; ni++)
#pragma unroll
            for (int i = 0; i < 4; i++) acc[mi][ni][i] = 0.0f;

    for (int k0 = 0; k0 < FCH; k0 += BK) {
        float4 va0 = make_float4(0,0,0,0), va1 = make_float4(0,0,0,0);
        if (avalid) {
            va0 = *(const float4*)(arp + k0 + ak);
            va1 = *(const float4*)(arp + k0 + ak + 4);
        }
        As[ak+0][arow] = __uint_as_float(f2tf(va0.x));
        As[ak+1][arow] = __uint_as_float(f2tf(va0.y));
        As[ak+2][arow] = __uint_as_float(f2tf(va0.z));
        As[ak+3][arow] = __uint_as_float(f2tf(va0.w));
        As[ak+4][arow] = __uint_as_float(f2tf(va1.x));
        As[ak+5][arow] = __uint_as_float(f2tf(va1.y));
        As[ak+6][arow] = __uint_as_float(f2tf(va1.z));
        As[ak+7][arow] = __uint_as_float(f2tf(va1.w));

        float4 vb = *(const float4*)(Bp + (size_t)(k0 + bk) * DD + n0 + bc);
        Bs[bk][bc+0] = __uint_as_float(f2tf(vb.x));
        Bs[bk][bc+1] = __uint_as_float(f2tf(vb.y));
        Bs[bk][bc+2] = __uint_as_float(f2tf(vb.z));
        Bs[bk][bc+3] = __uint_as_float(f2tf(vb.w));
        __syncthreads();

        TC_MAINLOOP
        __syncthreads();
    }

    // epilogue: scatter to out (RMW on later waves; bias on wave 0)
#pragma unroll
    for (int mi = 0; mi < 2; mi++) {
#pragma unroll
        for (int i = 0; i < 2; i++) {
            int lr = mwb + mi * 16 + gid + i * 8;
            int t  = srow[lr];
            if (t >= 0) {
#pragma unroll
                for (int ni = 0; ni < 4; ni++) {
                    int col = n0 + nwb + ni * 8 + tg * 2;
                    float2* cp = (float2*)(out + (size_t)t * DD + col);
                    float2 o;
                    if (accflag) {
                        o = *cp;
                        o.x += acc[mi][ni][i*2+0];
                        o.y += acc[mi][ni][i*2+1];
                    } else {
                        o.x = acc[mi][ni][i*2+0] + bias[col];
                        o.y = acc[mi][ni][i*2+1] + bias[col + 1];
                    }
                    *cp = o;
                }
            }
        }
    }
}

// ---------------- eager-load insurance (default-priority ctor only) ----------------
namespace {
struct ModulePreloader {
    ModulePreloader() {
        setenv("CUDA_MODULE_LOADING", "EAGER", 1);
        void* p = nullptr;
        (void)cudaGetSymbolAddress(&p, g_h);
        (void)cudaGetSymbolAddress(&p, g_eidx);
        (void)cudaGetSymbolAddress(&p, g_slot);
        (void)cudaGetSymbolAddress(&p, g_order);
        (void)cudaGetSymbolAddress(&p, g_cnt);
        (void)cudaGetSymbolAddress(&p, g_gsum);
        cudaFuncAttributes a;
        (void)cudaFuncGetAttributes(&a, (const void*)router_kernel);
        (void)cudaFuncGetAttributes(&a, (const void*)scan_kernel);
        (void)cudaFuncGetAttributes(&a, (const void*)gemm1_kernel);
        (void)cudaFuncGetAttributes(&a, (const void*)gemm2_kernel);
        (void)cudaFuncGetAttributes(&a, (const void*)zero_out_kernel);
        (void)cudaFuncGetAttributes(&a, (const void*)init_kernel);
    }
};
ModulePreloader g_module_preloader;
}

// ---------------- launch ----------------
extern "C" void kernel_launch(void* const* d_in, const int* in_sizes, int n_in,
                              void* d_out, int out_size) {
    const float* x   = (const float*)d_in[0];  // [B,S,D]
    const float* wr  = (const float*)d_in[1];  // [D,E]
    const float* w1  = (const float*)d_in[2];  // [E,D,F]
    const float* b1  = (const float*)d_in[3];  // [E,F]
    const float* w2  = (const float*)d_in[4];  // [E,F,D]
    const float* b2  = (const float*)d_in[5];  // [E,D]
    float* out = (float*)d_out;

    init_kernel<<<1, 32>>>();
    router_kernel<<<TT / 8, 256>>>(x, wr);
    zero_out_kernel<<<(TT * DD / 4) / 256, 256>>>(out);
    scan_kernel<<<1, 1024>>>(out, out_size);

    dim3 grid1(FCH / BN, (CAP + BM - 1) / BM, EE);   // 16 x 3 x 8 = 384
    dim3 grid2(DD  / BN, (CAP + BM - 1) / BM, EE);   // 16 x 3 x 8 = 384
    for (int c = 0; c < NWAVE; c++) {
        gemm1_kernel<<<grid1, 256>>>(x, w1, b1, c);
        gemm2_kernel<<<grid2, 256>>>(w2, b2, out, c, c > 0 ? 1 : 0);
    }
}

// round 11
// speedup vs baseline: 2.3991x; 1.3106x over previous
#include <cuda_runtime.h>
#include <cuda_bf16.h>
#include <math.h>
#include <stdlib.h>

// Problem constants (from reference setup_inputs)
#define BB 4
#define SS 2048
#define DD 1024
#define FF 4096
#define EE 8
#define TT (BB*SS)          // 8192 tokens
#define CAP 320             // int(2048/8 * 1.25)
#define FCH 1024            // F chunk per wave
#define NWAVE (FF/FCH)      // 4 waves

// ---------------- scratch (~10.6 MB total; no allocations allowed) ----------------
__device__ float g_h[EE * CAP * FCH];   // hidden activations, one F-chunk  [E, CAP, FCH]
__device__ int   g_eidx[TT];            // chosen expert per token
__device__ int   g_slot[TT];            // queue slot or -1 (dropped)
__device__ int   g_order[EE * CAP];     // token id for (expert, slot)
__device__ int   g_cnt[EE];             // capped per-expert token count
__device__ float g_gsum[EE];            // sum of softmax gates per expert

// ---------------- init: zero per-replay accumulators ----------------
__global__ void init_kernel() {
    if (threadIdx.x < EE) g_gsum[threadIdx.x] = 0.0f;
}

// ---------------- zero the output (dropped tokens stay zero) ----------------
__global__ void zero_out_kernel(float* __restrict__ out) {
    size_t i = (size_t)blockIdx.x * 256 + threadIdx.x;   // one float4 each
    float4* p = (float4*)out;
    p[i] = make_float4(0.f, 0.f, 0.f, 0.f);
}

// ---------------- router: logits, softmax stats, argmax ----------------
__global__ void router_kernel(const float* __restrict__ x,
                              const float* __restrict__ wr) {
    __shared__ float sg[EE];
    int tid  = threadIdx.x;
    int warp = tid >> 5;
    int lane = tid & 31;
    if (tid < EE) sg[tid] = 0.0f;
    __syncthreads();

    int t = blockIdx.x * 8 + warp;
    const float* xr = x + (size_t)t * DD;

    float p0=0.f,p1=0.f,p2=0.f,p3=0.f,p4=0.f,p5=0.f,p6=0.f,p7=0.f;
    for (int k = lane; k < DD; k += 32) {
        float xv = xr[k];
        const float4* w4 = (const float4*)(wr + (size_t)k * EE);
        float4 w0 = w4[0], w1 = w4[1];
        p0 = fmaf(xv, w0.x, p0); p1 = fmaf(xv, w0.y, p1);
        p2 = fmaf(xv, w0.z, p2); p3 = fmaf(xv, w0.w, p3);
        p4 = fmaf(xv, w1.x, p4); p5 = fmaf(xv, w1.y, p5);
        p6 = fmaf(xv, w1.z, p6); p7 = fmaf(xv, w1.w, p7);
    }
#pragma unroll
    for (int off = 16; off > 0; off >>= 1) {
        p0 += __shfl_xor_sync(0xFFFFFFFFu, p0, off);
        p1 += __shfl_xor_sync(0xFFFFFFFFu, p1, off);
        p2 += __shfl_xor_sync(0xFFFFFFFFu, p2, off);
        p3 += __shfl_xor_sync(0xFFFFFFFFu, p3, off);
        p4 += __shfl_xor_sync(0xFFFFFFFFu, p4, off);
        p5 += __shfl_xor_sync(0xFFFFFFFFu, p5, off);
        p6 += __shfl_xor_sync(0xFFFFFFFFu, p6, off);
        p7 += __shfl_xor_sync(0xFFFFFFFFu, p7, off);
    }

    if (lane == 0) {
        int best = 0; float bv = p0;
        if (p1 > bv) { bv = p1; best = 1; }
        if (p2 > bv) { bv = p2; best = 2; }
        if (p3 > bv) { bv = p3; best = 3; }
        if (p4 > bv) { bv = p4; best = 4; }
        if (p5 > bv) { bv = p5; best = 5; }
        if (p6 > bv) { bv = p6; best = 6; }
        if (p7 > bv) { bv = p7; best = 7; }
        g_eidx[t] = best;
        float m = bv;
        float e0 = __expf(p0 - m), e1 = __expf(p1 - m), e2 = __expf(p2 - m), e3 = __expf(p3 - m);
        float e4 = __expf(p4 - m), e5 = __expf(p5 - m), e6 = __expf(p6 - m), e7 = __expf(p7 - m);
        float inv = 1.0f / (e0+e1+e2+e3+e4+e5+e6+e7);
        atomicAdd(&sg[0], e0 * inv); atomicAdd(&sg[1], e1 * inv);
        atomicAdd(&sg[2], e2 * inv); atomicAdd(&sg[3], e3 * inv);
        atomicAdd(&sg[4], e4 * inv); atomicAdd(&sg[5], e5 * inv);
        atomicAdd(&sg[6], e6 * inv); atomicAdd(&sg[7], e7 * inv);
    }
    __syncthreads();
    if (tid < EE) atomicAdd(&g_gsum[tid], sg[tid]);
}

// ---------------- scan: stable per-expert positions + order table + loss ----------------
__global__ void scan_kernel(float* __restrict__ d_out, int out_size) {
    __shared__ int wtot[32][EE];
    __shared__ int totals[EE];
    __shared__ int sbase[1024][EE];     // 32 KB

    int tid  = threadIdx.x;
    int warp = tid >> 5;
    int lane = tid & 31;
    int base = tid * 8;

    int el0 = g_eidx[base+0], el1 = g_eidx[base+1], el2 = g_eidx[base+2], el3 = g_eidx[base+3];
    int el4 = g_eidx[base+4], el5 = g_eidx[base+5], el6 = g_eidx[base+6], el7 = g_eidx[base+7];

    int q1 = (el0==el1);
    int q2 = (el0==el2)+(el1==el2);
    int q3 = (el0==el3)+(el1==el3)+(el2==el3);
    int q4 = (el0==el4)+(el1==el4)+(el2==el4)+(el3==el4);
    int q5 = (el0==el5)+(el1==el5)+(el2==el5)+(el3==el5)+(el4==el5);
    int q6 = (el0==el6)+(el1==el6)+(el2==el6)+(el3==el6)+(el4==el6)+(el5==el6);
    int q7 = (el0==el7)+(el1==el7)+(el2==el7)+(el3==el7)+(el4==el7)+(el5==el7)+(el6==el7);

#pragma unroll
    for (int e = 0; e < EE; e++) {
        int cnt = (el0==e)+(el1==e)+(el2==e)+(el3==e)+(el4==e)+(el5==e)+(el6==e)+(el7==e);
        int s = cnt;
#pragma unroll
        for (int off = 1; off < 32; off <<= 1) {
            int o = __shfl_up_sync(0xFFFFFFFFu, s, off);
            if (lane >= off) s += o;
        }
        sbase[tid][e] = s - cnt;
        if (lane == 31) wtot[warp][e] = s;
    }
    __syncthreads();

    if (warp == 0) {
#pragma unroll
        for (int e = 0; e < EE; e++) {
            int v = wtot[lane][e], s = v;
#pragma unroll
            for (int off = 1; off < 32; off <<= 1) {
                int o = __shfl_up_sync(0xFFFFFFFFu, s, off);
                if (lane >= off) s += o;
            }
            wtot[lane][e] = s - v;
            if (lane == 31) totals[e] = s;
        }
    }
    __syncthreads();

#pragma unroll
    for (int e = 0; e < EE; e++) sbase[tid][e] += wtot[warp][e];
    __syncthreads();

    {
        int g0 = sbase[tid][el0];
        int g1 = sbase[tid][el1] + q1;
        int g2 = sbase[tid][el2] + q2;
        int g3 = sbase[tid][el3] + q3;
        int g4 = sbase[tid][el4] + q4;
        int g5 = sbase[tid][el5] + q5;
        int g6 = sbase[tid][el6] + q6;
        int g7 = sbase[tid][el7] + q7;
        g_slot[base+0] = (g0 < CAP) ? g0 : -1;
        g_slot[base+1] = (g1 < CAP) ? g1 : -1;
        g_slot[base+2] = (g2 < CAP) ? g2 : -1;
        g_slot[base+3] = (g3 < CAP) ? g3 : -1;
        g_slot[base+4] = (g4 < CAP) ? g4 : -1;
        g_slot[base+5] = (g5 < CAP) ? g5 : -1;
        g_slot[base+6] = (g6 < CAP) ? g6 : -1;
        g_slot[base+7] = (g7 < CAP) ? g7 : -1;
        if (g0 < CAP) g_order[el0*CAP + g0] = base+0;
        if (g1 < CAP) g_order[el1*CAP + g1] = base+1;
        if (g2 < CAP) g_order[el2*CAP + g2] = base+2;
        if (g3 < CAP) g_order[el3*CAP + g3] = base+3;
        if (g4 < CAP) g_order[el4*CAP + g4] = base+4;
        if (g5 < CAP) g_order[el5*CAP + g5] = base+5;
        if (g6 < CAP) g_order[el6*CAP + g6] = base+6;
        if (g7 < CAP) g_order[el7*CAP + g7] = base+7;
    }

    if (tid < EE) {
        int c = totals[tid];
        g_cnt[tid] = (c < CAP) ? c : CAP;
    }

    if (tid == 0 && out_size > TT * DD) {
        float loss = 0.0f;
        float invT = 1.0f / (float)TT;
#pragma unroll
        for (int e = 0; e < EE; e++)
            loss += ((float)totals[e] * invT) * (g_gsum[e] * invT);
        d_out[TT * DD] = (float)EE * loss;
    }
}

// ======== tf32 tensor-core GEMMs: cp.async double-buffered, 1 barrier/iter ========
// BM=128, BN=128, BK=16, 256 threads = 8 warps (2m x 4n), warp tile 64x32.
// As stored [m][k] (ld=20: conflict-free fragment loads), Bs [k][n] (ld=136).
// tf32 conversion (cvt.rna) applied at fragment-load time; fp32 accumulate.
#define BM 128
#define BN 128
#define BK 16
#define AS_LD (BK + 4)      // 20 floats
#define BS_LD (BN + 8)      // 136 floats

__device__ __forceinline__ unsigned f2tf(float f) {
    unsigned r;
    asm("cvt.rna.tf32.f32 %0, %1;" : "=r"(r) : "f"(f));
    return r;
}

__device__ __forceinline__ void cpa16(unsigned dst, const float* src) {
    asm volatile("cp.async.ca.shared.global [%0], [%1], 16;" :: "r"(dst), "l"(src));
}
__device__ __forceinline__ void cpa16z(unsigned dst, const float* src) {
    asm volatile("cp.async.ca.shared.global [%0], [%1], 16, 0;" :: "r"(dst), "l"(src));
}
#define CP_COMMIT() asm volatile("cp.async.commit_group;")
#define CP_WAIT0()  asm volatile("cp.async.wait_group 0;")

#define MMA_TF32(d, av, bv) \
    asm volatile("mma.sync.aligned.m16n8k8.row.col.f32.tf32.tf32.f32 " \
                 "{%0,%1,%2,%3}, {%4,%5,%6,%7}, {%8,%9}, {%0,%1,%2,%3};" \
                 : "+f"(d[0]), "+f"(d[1]), "+f"(d[2]), "+f"(d[3]) \
                 : "r"(av[0]), "r"(av[1]), "r"(av[2]), "r"(av[3]), \
                   "r"(bv[0]), "r"(bv[1]))

// Compute body: 2 ks-steps x (4m x 4n) MMAs from As/Bs buffer `buf`.
#define TC_COMPUTE(buf) \
    _Pragma("unroll") \
    for (int ks = 0; ks < 2; ks++) { \
        int k8 = ks * 8; \
        unsigned af[4][4]; \
        _Pragma("unroll") \
        for (int mi = 0; mi < 4; mi++) { \
            int r0 = mwb + mi * 16 + gid; \
            af[mi][0] = f2tf(As[buf][r0    ][k8 + tg    ]); \
            af[mi][1] = f2tf(As[buf][r0 + 8][k8 + tg    ]); \
            af[mi][2] = f2tf(As[buf][r0    ][k8 + tg + 4]); \
            af[mi][3] = f2tf(As[buf][r0 + 8][k8 + tg + 4]); \
        } \
        unsigned bf[4][2]; \
        _Pragma("unroll") \
        for (int ni = 0; ni < 4; ni++) { \
            int c0 = nwb + ni * 8 + gid; \
            bf[ni][0] = f2tf(Bs[buf][k8 + tg    ][c0]); \
            bf[ni][1] = f2tf(Bs[buf][k8 + tg + 4][c0]); \
        } \
        _Pragma("unroll") \
        for (int mi = 0; mi < 4; mi++) \
            _Pragma("unroll") \
            for (int ni = 0; ni < 4; ni++) \
                MMA_TF32(acc[mi][ni], af[mi], bf[ni]); \
    }

// ---------------- GEMM1: h_chunk = relu(gather(x) @ w1[:,:,chunk] + b1) ----------
__global__ __launch_bounds__(256)
void gemm1_kernel(const float* __restrict__ x, const float* __restrict__ w1,
                  const float* __restrict__ b1, int chunk) {
    int e  = blockIdx.z;
    int m0 = blockIdx.y * BM;
    int n0 = blockIdx.x * BN;
    const float* Bp   = w1 + (size_t)e * DD * FF + (size_t)chunk * FCH;  // row k stride FF
    const float* bias = b1 + (size_t)e * FF + (size_t)chunk * FCH;
    float* C = g_h + (size_t)e * CAP * FCH;
    int cnt = g_cnt[e];

    __shared__ int   srow[BM];
    __shared__ float As[2][BM][AS_LD];
    __shared__ float Bs[2][BK][BS_LD];

    int tid = threadIdx.x;
    if (tid < BM) {
        int m = m0 + tid;
        srow[tid] = (m < cnt) ? g_order[e * CAP + m] : -1;
    }
    __syncthreads();

    int wid = tid >> 5, lane = tid & 31;
    int gid = lane >> 2, tg = lane & 3;
    int mwb = (wid >> 2) * 64;          // 2 warps in m
    int nwb = (wid & 3) * 32;           // 4 warps in n

    int arow = tid >> 1;                // 0..127
    int ak   = (tid & 1) * 8;           // 0 or 8
    int bk   = tid >> 4;                // 0..15
    int bc   = (tid & 15) * 8;          // 0..120
    int gt   = srow[arow];
    const float* xrow = x + (size_t)((gt >= 0) ? gt : 0) * DD;
    const float* brow = Bp + (size_t)bk * FF + n0 + bc;

    unsigned aBase = (unsigned)__cvta_generic_to_shared(&As[0][0][0]);
    unsigned bBase = (unsigned)__cvta_generic_to_shared(&Bs[0][0][0]);
    unsigned aOff  = ((unsigned)(arow * AS_LD + ak)) * 4u;
    unsigned bOff  = ((unsigned)(bk * BS_LD + bc)) * 4u;
    const unsigned aStride = (unsigned)(BM * AS_LD) * 4u;
    const unsigned bStride = (unsigned)(BK * BS_LD) * 4u;

    float acc[4][4][4];
#pragma unroll
    for (int mi = 0; mi < 4; mi++)
#pragma unroll
        for (int ni = 0; ni < 4; ni++)
#pragma unroll
            for (int i = 0; i < 4; i++) acc[mi][ni][i] = 0.0f;

    // preload tile 0  (A source includes per-thread k offset `ak`)
    {
        unsigned ad = aBase + aOff, bd = bBase + bOff;
        if (gt >= 0) { cpa16(ad, xrow + ak); cpa16(ad + 16, xrow + ak + 4); }
        else         { cpa16z(ad, xrow); cpa16z(ad + 16, xrow); }
        cpa16(bd, brow); cpa16(bd + 16, brow + 4);
        CP_COMMIT();
    }

    const int nit = DD / BK;
    for (int it = 0; it < nit; it++) {
        CP_WAIT0();
        __syncthreads();    // tile `it` visible; all warps done with tile it-1
        if (it + 1 < nit) {
            int nb = (it + 1) & 1;
            int k0 = (it + 1) * BK;
            unsigned ad = aBase + nb * aStride + aOff;
            unsigned bd = bBase + nb * bStride + bOff;
            if (gt >= 0) { cpa16(ad, xrow + k0 + ak); cpa16(ad + 16, xrow + k0 + ak + 4); }
            else         { cpa16z(ad, xrow); cpa16z(ad + 16, xrow); }
            const float* bs = brow + (size_t)k0 * FF;
            cpa16(bd, bs); cpa16(bd + 16, bs + 4);
            CP_COMMIT();
        }
        int buf = it & 1;
        TC_COMPUTE(buf)
    }

    // epilogue: + bias, relu -> g_h
#pragma unroll
    for (int mi = 0; mi < 4; mi++) {
#pragma unroll
        for (int i = 0; i < 2; i++) {
            int row = m0 + mwb + mi * 16 + gid + i * 8;
            if (row < CAP) {
#pragma unroll
                for (int ni = 0; ni < 4; ni++) {
                    int col = n0 + nwb + ni * 8 + tg * 2;
                    float2 o;
                    o.x = fmaxf(acc[mi][ni][i*2+0] + bias[col],     0.0f);
                    o.y = fmaxf(acc[mi][ni][i*2+1] + bias[col + 1], 0.0f);
                    *(float2*)(C + (size_t)row * FCH + col) = o;
                }
            }
        }
    }
}

// ---------------- GEMM2: out[token] (+)= h_chunk @ w2[chunk] (+ b2 on wave 0) ----
__global__ __launch_bounds__(256)
void gemm2_kernel(const float* __restrict__ w2, const float* __restrict__ b2,
                  float* __restrict__ out, int chunk, int accflag) {
    int e  = blockIdx.z;
    int m0 = blockIdx.y * BM;
    int n0 = blockIdx.x * BN;
    const float* Ap   = g_h + (size_t)e * CAP * FCH;                         // row m stride FCH
    const float* Bp   = w2 + (size_t)e * FF * DD + (size_t)chunk * FCH * DD; // row k stride DD
    const float* bias = b2 + (size_t)e * DD;
    int cnt = g_cnt[e];

    __shared__ int   srow[BM];
    __shared__ float As[2][BM][AS_LD];
    __shared__ float Bs[2][BK][BS_LD];

    int tid = threadIdx.x;
    if (tid < BM) {
        int m = m0 + tid;
        srow[tid] = (m < cnt) ? g_order[e * CAP + m] : -1;
    }
    __syncthreads();

    int wid = tid >> 5, lane = tid & 31;
    int gid = lane >> 2, tg = lane & 3;
    int mwb = (wid >> 2) * 64;
    int nwb = (wid & 3) * 32;

    int arow = tid >> 1;
    int ak   = (tid & 1) * 8;
    int bk   = tid >> 4;
    int bc   = (tid & 15) * 8;
    int grow = m0 + arow;
    int avalid = (grow < CAP);
    const float* arp  = Ap + (size_t)(avalid ? grow : 0) * FCH;
    const float* brow = Bp + (size_t)bk * DD + n0 + bc;

    unsigned aBase = (unsigned)__cvta_generic_to_shared(&As[0][0][0]);
    unsigned bBase = (unsigned)__cvta_generic_to_shared(&Bs[0][0][0]);
    unsigned aOff  = ((unsigned)(arow * AS_LD + ak)) * 4u;
    unsigned bOff  = ((unsigned)(bk * BS_LD + bc)) * 4u;
    const unsigned aStride = (unsigned)(BM * AS_LD) * 4u;
    const unsigned bStride = (unsigned)(BK * BS_LD) * 4u;

    float acc[4][4][4];
#pragma unroll
    for (int mi = 0; mi < 4; mi++)
#pragma unroll
        for (int ni = 0; ni < 4; ni++)
#pragma unroll
            for (int i = 0; i < 4; i++) acc[mi][ni][i] = 0.0f;

    // preload tile 0
    {
        unsigned ad = aBase + aOff, bd = bBase + bOff;
        if (avalid) { cpa16(ad, arp + ak); cpa16(ad + 16, arp + ak + 4); }
        else        { cpa16z(ad, arp); cpa16z(ad + 16, arp); }
        cpa16(bd, brow); cpa16(bd + 16, brow + 4);
        CP_COMMIT();
    }

    const int nit = FCH / BK;
    for (int it = 0; it < nit; it++) {
        CP_WAIT0();
        __syncthreads();
        if (it + 1 < nit) {
            int nb = (it + 1) & 1;
            int k0 = (it + 1) * BK;
            unsigned ad = aBase + nb * aStride + aOff;
            unsigned bd = bBase + nb * bStride + bOff;
            if (avalid) { cpa16(ad, arp + k0 + ak); cpa16(ad + 16, arp + k0 + ak + 4); }
            else        { cpa16z(ad, arp); cpa16z(ad + 16, arp); }
            const float* bs = brow + (size_t)k0 * DD;
            cpa16(bd, bs); cpa16(bd + 16, bs + 4);
            CP_COMMIT();
        }
        int buf = it & 1;
        TC_COMPUTE(buf)
    }

    // epilogue: scatter to out (RMW on later waves; bias on wave 0)
#pragma unroll
    for (int mi = 0; mi < 4; mi++) {
#pragma unroll
        for (int i = 0; i < 2; i++) {
            int lr = mwb + mi * 16 + gid + i * 8;
            int t  = srow[lr];
            if (t >= 0) {
#pragma unroll
                for (int ni = 0; ni < 4; ni++) {
                    int col = n0 + nwb + ni * 8 + tg * 2;
                    float2* cp = (float2*)(out + (size_t)t * DD + col);
                    float2 o;
                    if (accflag) {
                        o = *cp;
                        o.x += acc[mi][ni][i*2+0];
                        o.y += acc[mi][ni][i*2+1];
                    } else {
                        o.x = acc[mi][ni][i*2+0] + bias[col];
                        o.y = acc[mi][ni][i*2+1] + bias[col + 1];
                    }
                    *cp = o;
                }
            }
        }
    }
}

// ---------------- eager-load insurance (default-priority ctor only) ----------------
namespace {
struct ModulePreloader {
    ModulePreloader() {
        setenv("CUDA_MODULE_LOADING", "EAGER", 1);
        void* p = nullptr;
        (void)cudaGetSymbolAddress(&p, g_h);
        (void)cudaGetSymbolAddress(&p, g_eidx);
        (void)cudaGetSymbolAddress(&p, g_slot);
        (void)cudaGetSymbolAddress(&p, g_order);
        (void)cudaGetSymbolAddress(&p, g_cnt);
        (void)cudaGetSymbolAddress(&p, g_gsum);
        cudaFuncAttributes a;
        (void)cudaFuncGetAttributes(&a, (const void*)router_kernel);
        (void)cudaFuncGetAttributes(&a, (const void*)scan_kernel);
        (void)cudaFuncGetAttributes(&a, (const void*)gemm1_kernel);
        (void)cudaFuncGetAttributes(&a, (const void*)gemm2_kernel);
        (void)cudaFuncGetAttributes(&a, (const void*)zero_out_kernel);
        (void)cudaFuncGetAttributes(&a, (const void*)init_kernel);
    }
};
ModulePreloader g_module_preloader;
}

// ---------------- launch ----------------
extern "C" void kernel_launch(void* const* d_in, const int* in_sizes, int n_in,
                              void* d_out, int out_size) {
    const float* x   = (const float*)d_in[0];  // [B,S,D]
    const float* wr  = (const float*)d_in[1];  // [D,E]
    const float* w1  = (const float*)d_in[2];  // [E,D,F]
    const float* b1  = (const float*)d_in[3];  // [E,F]
    const float* w2  = (const float*)d_in[4];  // [E,F,D]
    const float* b2  = (const float*)d_in[5];  // [E,D]
    float* out = (float*)d_out;

    init_kernel<<<1, 32>>>();
    router_kernel<<<TT / 8, 256>>>(x, wr);
    zero_out_kernel<<<(TT * DD / 4) / 256, 256>>>(out);
    scan_kernel<<<1, 1024>>>(out, out_size);

    dim3 grid1(FCH / BN, (CAP + BM - 1) / BM, EE);   // 8 x 3 x 8 = 192
    dim3 grid2(DD  / BN, (CAP + BM - 1) / BM, EE);   // 8 x 3 x 8 = 192
    for (int c = 0; c < NWAVE; c++) {
        gemm1_kernel<<<grid1, 256>>>(x, w1, b1, c);
        gemm2_kernel<<<grid2, 256>>>(w2, b2, out, c, c > 0 ? 1 : 0);
    }
}

// round 13
// speedup vs baseline: 2.4236x; 1.0102x over previous
#include <cuda_runtime.h>
#include <cuda_bf16.h>
#include <math.h>
#include <stdlib.h>
#include <stdint.h>

// Problem constants
#define BB 4
#define SS 2048
#define DD 1024
#define FF 4096
#define EE 8
#define TT (BB*SS)          // 8192 tokens
#define CAP 320             // int(2048/8 * 1.25)
#define FCH 1024            // F chunk per wave
#define NWAVE (FF/FCH)      // 4 waves

// ---------------- scratch (~10.6 MB; no allocations allowed) ----------------
__device__ float g_h[EE * CAP * FCH];
__device__ int   g_eidx[TT];
__device__ int   g_slot[TT];
__device__ int   g_order[EE * CAP];
__device__ int   g_cnt[EE];
__device__ float g_gsum[EE];

// ---------------- init ----------------
__global__ void init_kernel() {
    if (threadIdx.x < EE) g_gsum[threadIdx.x] = 0.0f;
}

__global__ void zero_out_kernel(float* __restrict__ out) {
    size_t i = (size_t)blockIdx.x * 256 + threadIdx.x;
    ((float4*)out)[i] = make_float4(0.f, 0.f, 0.f, 0.f);
}

// ---------------- router ----------------
__global__ void router_kernel(const float* __restrict__ x,
                              const float* __restrict__ wr) {
    __shared__ float sg[EE];
    int tid  = threadIdx.x;
    int warp = tid >> 5;
    int lane = tid & 31;
    if (tid < EE) sg[tid] = 0.0f;
    __syncthreads();

    int t = blockIdx.x * 8 + warp;
    const float* xr = x + (size_t)t * DD;

    float p0=0.f,p1=0.f,p2=0.f,p3=0.f,p4=0.f,p5=0.f,p6=0.f,p7=0.f;
    for (int k = lane; k < DD; k += 32) {
        float xv = xr[k];
        const float4* w4 = (const float4*)(wr + (size_t)k * EE);
        float4 w0 = w4[0], w1 = w4[1];
        p0 = fmaf(xv, w0.x, p0); p1 = fmaf(xv, w0.y, p1);
        p2 = fmaf(xv, w0.z, p2); p3 = fmaf(xv, w0.w, p3);
        p4 = fmaf(xv, w1.x, p4); p5 = fmaf(xv, w1.y, p5);
        p6 = fmaf(xv, w1.z, p6); p7 = fmaf(xv, w1.w, p7);
    }
#pragma unroll
    for (int off = 16; off > 0; off >>= 1) {
        p0 += __shfl_xor_sync(0xFFFFFFFFu, p0, off);
        p1 += __shfl_xor_sync(0xFFFFFFFFu, p1, off);
        p2 += __shfl_xor_sync(0xFFFFFFFFu, p2, off);
        p3 += __shfl_xor_sync(0xFFFFFFFFu, p3, off);
        p4 += __shfl_xor_sync(0xFFFFFFFFu, p4, off);
        p5 += __shfl_xor_sync(0xFFFFFFFFu, p5, off);
        p6 += __shfl_xor_sync(0xFFFFFFFFu, p6, off);
        p7 += __shfl_xor_sync(0xFFFFFFFFu, p7, off);
    }

    if (lane == 0) {
        int best = 0; float bv = p0;
        if (p1 > bv) { bv = p1; best = 1; }
        if (p2 > bv) { bv = p2; best = 2; }
        if (p3 > bv) { bv = p3; best = 3; }
        if (p4 > bv) { bv = p4; best = 4; }
        if (p5 > bv) { bv = p5; best = 5; }
        if (p6 > bv) { bv = p6; best = 6; }
        if (p7 > bv) { bv = p7; best = 7; }
        g_eidx[t] = best;
        float m = bv;
        float e0 = __expf(p0 - m), e1 = __expf(p1 - m), e2 = __expf(p2 - m), e3 = __expf(p3 - m);
        float e4 = __expf(p4 - m), e5 = __expf(p5 - m), e6 = __expf(p6 - m), e7 = __expf(p7 - m);
        float inv = 1.0f / (e0+e1+e2+e3+e4+e5+e6+e7);
        atomicAdd(&sg[0], e0 * inv); atomicAdd(&sg[1], e1 * inv);
        atomicAdd(&sg[2], e2 * inv); atomicAdd(&sg[3], e3 * inv);
        atomicAdd(&sg[4], e4 * inv); atomicAdd(&sg[5], e5 * inv);
        atomicAdd(&sg[6], e6 * inv); atomicAdd(&sg[7], e7 * inv);
    }
    __syncthreads();
    if (tid < EE) atomicAdd(&g_gsum[tid], sg[tid]);
}

// ---------------- scan ----------------
__global__ void scan_kernel(float* __restrict__ d_out, int out_size) {
    __shared__ int wtot[32][EE];
    __shared__ int totals[EE];
    __shared__ int sbase[1024][EE];

    int tid  = threadIdx.x;
    int warp = tid >> 5;
    int lane = tid & 31;
    int base = tid * 8;

    int el0 = g_eidx[base+0], el1 = g_eidx[base+1], el2 = g_eidx[base+2], el3 = g_eidx[base+3];
    int el4 = g_eidx[base+4], el5 = g_eidx[base+5], el6 = g_eidx[base+6], el7 = g_eidx[base+7];

    int q1 = (el0==el1);
    int q2 = (el0==el2)+(el1==el2);
    int q3 = (el0==el3)+(el1==el3)+(el2==el3);
    int q4 = (el0==el4)+(el1==el4)+(el2==el4)+(el3==el4);
    int q5 = (el0==el5)+(el1==el5)+(el2==el5)+(el3==el5)+(el4==el5);
    int q6 = (el0==el6)+(el1==el6)+(el2==el6)+(el3==el6)+(el4==el6)+(el5==el6);
    int q7 = (el0==el7)+(el1==el7)+(el2==el7)+(el3==el7)+(el4==el7)+(el5==el7)+(el6==el7);

#pragma unroll
    for (int e = 0; e < EE; e++) {
        int cnt = (el0==e)+(el1==e)+(el2==e)+(el3==e)+(el4==e)+(el5==e)+(el6==e)+(el7==e);
        int s = cnt;
#pragma unroll
        for (int off = 1; off < 32; off <<= 1) {
            int o = __shfl_up_sync(0xFFFFFFFFu, s, off);
            if (lane >= off) s += o;
        }
        sbase[tid][e] = s - cnt;
        if (lane == 31) wtot[warp][e] = s;
    }
    __syncthreads();

    if (warp == 0) {
#pragma unroll
        for (int e = 0; e < EE; e++) {
            int v = wtot[lane][e], s = v;
#pragma unroll
            for (int off = 1; off < 32; off <<= 1) {
                int o = __shfl_up_sync(0xFFFFFFFFu, s, off);
                if (lane >= off) s += o;
            }
            wtot[lane][e] = s - v;
            if (lane == 31) totals[e] = s;
        }
    }
    __syncthreads();

#pragma unroll
    for (int e = 0; e < EE; e++) sbase[tid][e] += wtot[warp][e];
    __syncthreads();

    {
        int g0 = sbase[tid][el0];
        int g1 = sbase[tid][el1] + q1;
        int g2 = sbase[tid][el2] + q2;
        int g3 = sbase[tid][el3] + q3;
        int g4 = sbase[tid][el4] + q4;
        int g5 = sbase[tid][el5] + q5;
        int g6 = sbase[tid][el6] + q6;
        int g7 = sbase[tid][el7] + q7;
        g_slot[base+0] = (g0 < CAP) ? g0 : -1;
        g_slot[base+1] = (g1 < CAP) ? g1 : -1;
        g_slot[base+2] = (g2 < CAP) ? g2 : -1;
        g_slot[base+3] = (g3 < CAP) ? g3 : -1;
        g_slot[base+4] = (g4 < CAP) ? g4 : -1;
        g_slot[base+5] = (g5 < CAP) ? g5 : -1;
        g_slot[base+6] = (g6 < CAP) ? g6 : -1;
        g_slot[base+7] = (g7 < CAP) ? g7 : -1;
        if (g0 < CAP) g_order[el0*CAP + g0] = base+0;
        if (g1 < CAP) g_order[el1*CAP + g1] = base+1;
        if (g2 < CAP) g_order[el2*CAP + g2] = base+2;
        if (g3 < CAP) g_order[el3*CAP + g3] = base+3;
        if (g4 < CAP) g_order[el4*CAP + g4] = base+4;
        if (g5 < CAP) g_order[el5*CAP + g5] = base+5;
        if (g6 < CAP) g_order[el6*CAP + g6] = base+6;
        if (g7 < CAP) g_order[el7*CAP + g7] = base+7;
    }

    if (tid < EE) {
        int c = totals[tid];
        g_cnt[tid] = (c < CAP) ? c : CAP;
    }

    if (tid == 0 && out_size > TT * DD) {
        float loss = 0.0f;
        float invT = 1.0f / (float)TT;
#pragma unroll
        for (int e = 0; e < EE; e++)
            loss += ((float)totals[e] * invT) * (g_gsum[e] * invT);
        d_out[TT * DD] = (float)EE * loss;
    }
}

// ======== tf32 mma.sync GEMMs: 4-stage cp.async pipeline ========
// BM=128, BN=128, BK=16, 256 threads = 8 warps (2m x 4n), warp tile 64x32.
// As [m][k] ld=20 (conflict-free frag loads), Bs [k][n] ld=136.
#define BM 128
#define BN 128
#define BK 16
#define STAGES 4
#define AS_LD (BK + 4)      // 20 floats
#define BS_LD (BN + 8)      // 136 floats

// dynamic smem layout (bytes)
#define SM_SROW   0
#define SM_A      1024
#define A_BUF_B   (BM * AS_LD * 4)          // 10240
#define SM_B      (SM_A + STAGES * A_BUF_B) // 1024 + 40960
#define B_BUF_B   (BK * BS_LD * 4)          // 8704
#define SMEM_TOT  (SM_B + STAGES * B_BUF_B) // 76800

__device__ __forceinline__ unsigned f2tf(float f) {
    unsigned r;
    asm("cvt.rna.tf32.f32 %0, %1;" : "=r"(r) : "f"(f));
    return r;
}

__device__ __forceinline__ void cpa16(unsigned dst, const float* src) {
    asm volatile("cp.async.ca.shared.global [%0], [%1], 16;" :: "r"(dst), "l"(src));
}
__device__ __forceinline__ void cpa16z(unsigned dst, const float* src) {
    asm volatile("cp.async.ca.shared.global [%0], [%1], 16, 0;" :: "r"(dst), "l"(src));
}
#define CP_COMMIT() asm volatile("cp.async.commit_group;")
#define CP_WAIT2()  asm volatile("cp.async.wait_group 2;")

#define MMA_TF32(d, av, bv) \
    asm volatile("mma.sync.aligned.m16n8k8.row.col.f32.tf32.tf32.f32 " \
                 "{%0,%1,%2,%3}, {%4,%5,%6,%7}, {%8,%9}, {%0,%1,%2,%3};" \
                 : "+f"(d[0]), "+f"(d[1]), "+f"(d[2]), "+f"(d[3]) \
                 : "r"(av[0]), "r"(av[1]), "r"(av[2]), "r"(av[3]), \
                   "r"(bv[0]), "r"(bv[1]))

// compute one BK tile from buffers Asb/Bsb into acc
__device__ __forceinline__ void tc_compute(const float (*Asb)[AS_LD],
                                           const float (*Bsb)[BS_LD],
                                           float (*acc)[4][4],
                                           int mwb, int nwb, int gid, int tg) {
#pragma unroll
    for (int ks = 0; ks < 2; ks++) {
        int k8 = ks * 8;
        unsigned af[4][4];
#pragma unroll
        for (int mi = 0; mi < 4; mi++) {
            int r0 = mwb + mi * 16 + gid;
            af[mi][0] = f2tf(Asb[r0    ][k8 + tg    ]);
            af[mi][1] = f2tf(Asb[r0 + 8][k8 + tg    ]);
            af[mi][2] = f2tf(Asb[r0    ][k8 + tg + 4]);
            af[mi][3] = f2tf(Asb[r0 + 8][k8 + tg + 4]);
        }
        unsigned bf[4][2];
#pragma unroll
        for (int ni = 0; ni < 4; ni++) {
            int c0 = nwb + ni * 8 + gid;
            bf[ni][0] = f2tf(Bsb[k8 + tg    ][c0]);
            bf[ni][1] = f2tf(Bsb[k8 + tg + 4][c0]);
        }
#pragma unroll
        for (int mi = 0; mi < 4; mi++)
#pragma unroll
            for (int ni = 0; ni < 4; ni++)
                MMA_TF32(acc[mi][ni], af[mi], bf[ni]);
    }
}

// ---------------- GEMM1: h_chunk = relu(gather(x) @ w1[:,:,chunk] + b1) ----------
__global__ __launch_bounds__(256)
void gemm1_kernel(const float* __restrict__ x, const float* __restrict__ w1,
                  const float* __restrict__ b1, int chunk) {
    extern __shared__ char smem[];
    int e  = blockIdx.z;
    int m0 = blockIdx.y * BM;
    int n0 = blockIdx.x * BN;
    const float* Bp   = w1 + (size_t)e * DD * FF + (size_t)chunk * FCH;  // row k stride FF
    const float* bias = b1 + (size_t)e * FF + (size_t)chunk * FCH;
    float* C = g_h + (size_t)e * CAP * FCH;
    int cnt = g_cnt[e];

    int* srow = (int*)(smem + SM_SROW);
    int tid = threadIdx.x;
    if (tid < BM) {
        int m = m0 + tid;
        srow[tid] = (m < cnt) ? g_order[e * CAP + m] : -1;
    }
    __syncthreads();

    int wid = tid >> 5, lane = tid & 31;
    int gid = lane >> 2, tg = lane & 3;
    int mwb = (wid >> 2) * 64;
    int nwb = (wid & 3) * 32;

    int arow = tid >> 1;
    int ak   = (tid & 1) * 8;
    int bk   = tid >> 4;
    int bc   = (tid & 15) * 8;
    int gt   = srow[arow];
    const float* xrow = x + (size_t)((gt >= 0) ? gt : 0) * DD;
    const float* brow = Bp + (size_t)bk * FF + n0 + bc;

    unsigned aBase = (unsigned)__cvta_generic_to_shared(smem + SM_A);
    unsigned bBase = (unsigned)__cvta_generic_to_shared(smem + SM_B);
    unsigned aOff  = ((unsigned)(arow * AS_LD + ak)) * 4u;
    unsigned bOff  = ((unsigned)(bk * BS_LD + bc)) * 4u;

    float acc[4][4][4];
#pragma unroll
    for (int mi = 0; mi < 4; mi++)
#pragma unroll
        for (int ni = 0; ni < 4; ni++)
#pragma unroll
            for (int i = 0; i < 4; i++) acc[mi][ni][i] = 0.0f;

    const int nit = DD / BK;   // 64
    // prologue: stages 0..2
#pragma unroll
    for (int s = 0; s < STAGES - 1; s++) {
        unsigned ad = aBase + (unsigned)s * A_BUF_B + aOff;
        unsigned bd = bBase + (unsigned)s * B_BUF_B + bOff;
        int k0 = s * BK;
        if (gt >= 0) { cpa16(ad, xrow + k0 + ak); cpa16(ad + 16, xrow + k0 + ak + 4); }
        else         { cpa16z(ad, xrow); cpa16z(ad + 16, xrow); }
        const float* bs = brow + (size_t)k0 * FF;
        cpa16(bd, bs); cpa16(bd + 16, bs + 4);
        CP_COMMIT();
    }

    for (int t = 0; t < nit; t++) {
        CP_WAIT2();
        __syncthreads();   // tile t ready; all warps done with tile t-1 (whose buffer we refill)
        int pf = t + STAGES - 1;
        if (pf < nit) {
            int nb = pf & (STAGES - 1);
            unsigned ad = aBase + (unsigned)nb * A_BUF_B + aOff;
            unsigned bd = bBase + (unsigned)nb * B_BUF_B + bOff;
            int k0 = pf * BK;
            if (gt >= 0) { cpa16(ad, xrow + k0 + ak); cpa16(ad + 16, xrow + k0 + ak + 4); }
            else         { cpa16z(ad, xrow); cpa16z(ad + 16, xrow); }
            const float* bs = brow + (size_t)k0 * FF;
            cpa16(bd, bs); cpa16(bd + 16, bs + 4);
        }
        CP_COMMIT();   // committed every iter so wait_group 2 always implies tile t complete
        int buf = t & (STAGES - 1);
        tc_compute((const float(*)[AS_LD])(smem + SM_A + buf * A_BUF_B),
                   (const float(*)[BS_LD])(smem + SM_B + buf * B_BUF_B),
                   acc, mwb, nwb, gid, tg);
    }

    // epilogue: + bias, relu -> g_h
#pragma unroll
    for (int mi = 0; mi < 4; mi++) {
#pragma unroll
        for (int i = 0; i < 2; i++) {
            int row = m0 + mwb + mi * 16 + gid + i * 8;
            if (row < CAP) {
#pragma unroll
                for (int ni = 0; ni < 4; ni++) {
                    int col = n0 + nwb + ni * 8 + tg * 2;
                    float2 o;
                    o.x = fmaxf(acc[mi][ni][i*2+0] + bias[col],     0.0f);
                    o.y = fmaxf(acc[mi][ni][i*2+1] + bias[col + 1], 0.0f);
                    *(float2*)(C + (size_t)row * FCH + col) = o;
                }
            }
        }
    }
}

// ---------------- GEMM2: out[token] (+)= h_chunk @ w2[chunk] (+ b2 on wave 0) ----
__global__ __launch_bounds__(256)
void gemm2_kernel(const float* __restrict__ w2, const float* __restrict__ b2,
                  float* __restrict__ out, int chunk, int accflag) {
    extern __shared__ char smem[];
    int e  = blockIdx.z;
    int m0 = blockIdx.y * BM;
    int n0 = blockIdx.x * BN;
    const float* Ap   = g_h + (size_t)e * CAP * FCH;
    const float* Bp   = w2 + (size_t)e * FF * DD + (size_t)chunk * FCH * DD;
    const float* bias = b2 + (size_t)e * DD;
    int cnt = g_cnt[e];

    int* srow = (int*)(smem + SM_SROW);
    int tid = threadIdx.x;
    if (tid < BM) {
        int m = m0 + tid;
        srow[tid] = (m < cnt) ? g_order[e * CAP + m] : -1;
    }
    __syncthreads();

    int wid = tid >> 5, lane = tid & 31;
    int gid = lane >> 2, tg = lane & 3;
    int mwb = (wid >> 2) * 64;
    int nwb = (wid & 3) * 32;

    int arow = tid >> 1;
    int ak   = (tid & 1) * 8;
    int bk   = tid >> 4;
    int bc   = (tid & 15) * 8;
    int grow = m0 + arow;
    int avalid = (grow < CAP);
    const float* arp  = Ap + (size_t)(avalid ? grow : 0) * FCH;
    const float* brow = Bp + (size_t)bk * DD + n0 + bc;

    unsigned aBase = (unsigned)__cvta_generic_to_shared(smem + SM_A);
    unsigned bBase = (unsigned)__cvta_generic_to_shared(smem + SM_B);
    unsigned aOff  = ((unsigned)(arow * AS_LD + ak)) * 4u;
    unsigned bOff  = ((unsigned)(bk * BS_LD + bc)) * 4u;

    float acc[4][4][4];
#pragma unroll
    for (int mi = 0; mi < 4; mi++)
#pragma unroll
        for (int ni = 0; ni < 4; ni++)
#pragma unroll
            for (int i = 0; i < 4; i++) acc[mi][ni][i] = 0.0f;

    const int nit = FCH / BK;  // 64
#pragma unroll
    for (int s = 0; s < STAGES - 1; s++) {
        unsigned ad = aBase + (unsigned)s * A_BUF_B + aOff;
        unsigned bd = bBase + (unsigned)s * B_BUF_B + bOff;
        int k0 = s * BK;
        if (avalid) { cpa16(ad, arp + k0 + ak); cpa16(ad + 16, arp + k0 + ak + 4); }
        else        { cpa16z(ad, arp); cpa16z(ad + 16, arp); }
        const float* bs = brow + (size_t)k0 * DD;
        cpa16(bd, bs); cpa16(bd + 16, bs + 4);
        CP_COMMIT();
    }

    for (int t = 0; t < nit; t++) {
        CP_WAIT2();
        __syncthreads();
        int pf = t + STAGES - 1;
        if (pf < nit) {
            int nb = pf & (STAGES - 1);
            unsigned ad = aBase + (unsigned)nb * A_BUF_B + aOff;
            unsigned bd = bBase + (unsigned)nb * B_BUF_B + bOff;
            int k0 = pf * BK;
            if (avalid) { cpa16(ad, arp + k0 + ak); cpa16(ad + 16, arp + k0 + ak + 4); }
            else        { cpa16z(ad, arp); cpa16z(ad + 16, arp); }
            const float* bs = brow + (size_t)k0 * DD;
            cpa16(bd, bs); cpa16(bd + 16, bs + 4);
        }
        CP_COMMIT();
        int buf = t & (STAGES - 1);
        tc_compute((const float(*)[AS_LD])(smem + SM_A + buf * A_BUF_B),
                   (const float(*)[BS_LD])(smem + SM_B + buf * B_BUF_B),
                   acc, mwb, nwb, gid, tg);
    }

    // epilogue: scatter to out (RMW on later waves; bias on wave 0)
#pragma unroll
    for (int mi = 0; mi < 4; mi++) {
#pragma unroll
        for (int i = 0; i < 2; i++) {
            int lr = mwb + mi * 16 + gid + i * 8;
            int t  = srow[lr];
            if (t >= 0) {
#pragma unroll
                for (int ni = 0; ni < 4; ni++) {
                    int col = n0 + nwb + ni * 8 + tg * 2;
                    float2* cp = (float2*)(out + (size_t)t * DD + col);
                    float2 o;
                    if (accflag) {
                        o = *cp;
                        o.x += acc[mi][ni][i*2+0];
                        o.y += acc[mi][ni][i*2+1];
                    } else {
                        o.x = acc[mi][ni][i*2+0] + bias[col];
                        o.y = acc[mi][ni][i*2+1] + bias[col + 1];
                    }
                    *cp = o;
                }
            }
        }
    }
}

// ---------------- eager-load + smem attr (default-priority ctor) ----------------
namespace {
struct ModulePreloader {
    ModulePreloader() {
        setenv("CUDA_MODULE_LOADING", "EAGER", 1);
        void* p = nullptr;
        (void)cudaGetSymbolAddress(&p, g_h);
        (void)cudaGetSymbolAddress(&p, g_eidx);
        (void)cudaGetSymbolAddress(&p, g_slot);
        (void)cudaGetSymbolAddress(&p, g_order);
        (void)cudaGetSymbolAddress(&p, g_cnt);
        (void)cudaGetSymbolAddress(&p, g_gsum);
        cudaFuncAttributes a;
        (void)cudaFuncGetAttributes(&a, (const void*)router_kernel);
        (void)cudaFuncGetAttributes(&a, (const void*)scan_kernel);
        (void)cudaFuncGetAttributes(&a, (const void*)gemm1_kernel);
        (void)cudaFuncGetAttributes(&a, (const void*)gemm2_kernel);
        (void)cudaFuncGetAttributes(&a, (const void*)zero_out_kernel);
        (void)cudaFuncGetAttributes(&a, (const void*)init_kernel);
        (void)cudaFuncSetAttribute((const void*)gemm1_kernel,
                                   cudaFuncAttributeMaxDynamicSharedMemorySize, SMEM_TOT);
        (void)cudaFuncSetAttribute((const void*)gemm2_kernel,
                                   cudaFuncAttributeMaxDynamicSharedMemorySize, SMEM_TOT);
    }
};
ModulePreloader g_module_preloader;
}

// ---------------- launch ----------------
extern "C" void kernel_launch(void* const* d_in, const int* in_sizes, int n_in,
                              void* d_out, int out_size) {
    const float* x   = (const float*)d_in[0];
    const float* wr  = (const float*)d_in[1];
    const float* w1  = (const float*)d_in[2];
    const float* b1  = (const float*)d_in[3];
    const float* w2  = (const float*)d_in[4];
    const float* b2  = (const float*)d_in[5];
    float* out = (float*)d_out;

    (void)cudaFuncSetAttribute((const void*)gemm1_kernel,
                               cudaFuncAttributeMaxDynamicSharedMemorySize, SMEM_TOT);
    (void)cudaFuncSetAttribute((const void*)gemm2_kernel,
                               cudaFuncAttributeMaxDynamicSharedMemorySize, SMEM_TOT);

    init_kernel<<<1, 32>>>();
    router_kernel<<<TT / 8, 256>>>(x, wr);
    zero_out_kernel<<<(TT * DD / 4) / 256, 256>>>(out);
    scan_kernel<<<1, 1024>>>(out, out_size);

    dim3 grid1(FCH / BN, (CAP + BM - 1) / BM, EE);   // 8 x 3 x 8 = 192
    dim3 grid2(DD  / BN, (CAP + BM - 1) / BM, EE);   // 8 x 3 x 8 = 192
    for (int c = 0; c < NWAVE; c++) {
        gemm1_kernel<<<grid1, 256, SMEM_TOT>>>(x, w1, b1, c);
        gemm2_kernel<<<grid2, 256, SMEM_TOT>>>(w2, b2, out, c, c > 0 ? 1 : 0);
    }
}

// round 14
// speedup vs baseline: 3.7842x; 1.5614x over previous
#include <cuda_runtime.h>
#include <cuda_bf16.h>
#include <math.h>
#include <stdlib.h>
#include <stdint.h>

// Problem constants
#define BB 4
#define SS 2048
#define DD 1024
#define FF 4096
#define EE 8
#define TT (BB*SS)          // 8192 tokens
#define CAP 320             // int(2048/8 * 1.25)
#define FCH 1024            // F chunk per wave
#define NWAVE (FF/FCH)      // 4 waves

// ---------------- scratch (~10.6 MB; no allocations allowed) ----------------
__device__ float g_h[EE * CAP * FCH];
__device__ int   g_eidx[TT];
__device__ int   g_slot[TT];
__device__ int   g_order[EE * CAP];
__device__ int   g_cnt[EE];
__device__ float g_gsum[EE];

// ---------------- init ----------------
__global__ void init_kernel() {
    if (threadIdx.x < EE) g_gsum[threadIdx.x] = 0.0f;
}

__global__ void zero_out_kernel(float* __restrict__ out) {
    size_t i = (size_t)blockIdx.x * 256 + threadIdx.x;
    ((float4*)out)[i] = make_float4(0.f, 0.f, 0.f, 0.f);
}

// ---------------- router ----------------
__global__ void router_kernel(const float* __restrict__ x,
                              const float* __restrict__ wr) {
    __shared__ float sg[EE];
    int tid  = threadIdx.x;
    int warp = tid >> 5;
    int lane = tid & 31;
    if (tid < EE) sg[tid] = 0.0f;
    __syncthreads();

    int t = blockIdx.x * 8 + warp;
    const float* xr = x + (size_t)t * DD;

    float p0=0.f,p1=0.f,p2=0.f,p3=0.f,p4=0.f,p5=0.f,p6=0.f,p7=0.f;
    for (int k = lane; k < DD; k += 32) {
        float xv = xr[k];
        const float4* w4 = (const float4*)(wr + (size_t)k * EE);
        float4 w0 = w4[0], w1 = w4[1];
        p0 = fmaf(xv, w0.x, p0); p1 = fmaf(xv, w0.y, p1);
        p2 = fmaf(xv, w0.z, p2); p3 = fmaf(xv, w0.w, p3);
        p4 = fmaf(xv, w1.x, p4); p5 = fmaf(xv, w1.y, p5);
        p6 = fmaf(xv, w1.z, p6); p7 = fmaf(xv, w1.w, p7);
    }
#pragma unroll
    for (int off = 16; off > 0; off >>= 1) {
        p0 += __shfl_xor_sync(0xFFFFFFFFu, p0, off);
        p1 += __shfl_xor_sync(0xFFFFFFFFu, p1, off);
        p2 += __shfl_xor_sync(0xFFFFFFFFu, p2, off);
        p3 += __shfl_xor_sync(0xFFFFFFFFu, p3, off);
        p4 += __shfl_xor_sync(0xFFFFFFFFu, p4, off);
        p5 += __shfl_xor_sync(0xFFFFFFFFu, p5, off);
        p6 += __shfl_xor_sync(0xFFFFFFFFu, p6, off);
        p7 += __shfl_xor_sync(0xFFFFFFFFu, p7, off);
    }

    if (lane == 0) {
        int best = 0; float bv = p0;
        if (p1 > bv) { bv = p1; best = 1; }
        if (p2 > bv) { bv = p2; best = 2; }
        if (p3 > bv) { bv = p3; best = 3; }
        if (p4 > bv) { bv = p4; best = 4; }
        if (p5 > bv) { bv = p5; best = 5; }
        if (p6 > bv) { bv = p6; best = 6; }
        if (p7 > bv) { bv = p7; best = 7; }
        g_eidx[t] = best;
        float m = bv;
        float e0 = __expf(p0 - m), e1 = __expf(p1 - m), e2 = __expf(p2 - m), e3 = __expf(p3 - m);
        float e4 = __expf(p4 - m), e5 = __expf(p5 - m), e6 = __expf(p6 - m), e7 = __expf(p7 - m);
        float inv = 1.0f / (e0+e1+e2+e3+e4+e5+e6+e7);
        atomicAdd(&sg[0], e0 * inv); atomicAdd(&sg[1], e1 * inv);
        atomicAdd(&sg[2], e2 * inv); atomicAdd(&sg[3], e3 * inv);
        atomicAdd(&sg[4], e4 * inv); atomicAdd(&sg[5], e5 * inv);
        atomicAdd(&sg[6], e6 * inv); atomicAdd(&sg[7], e7 * inv);
    }
    __syncthreads();
    if (tid < EE) atomicAdd(&g_gsum[tid], sg[tid]);
}

// ---------------- scan ----------------
__global__ void scan_kernel(float* __restrict__ d_out, int out_size) {
    __shared__ int wtot[32][EE];
    __shared__ int totals[EE];
    __shared__ int sbase[1024][EE];

    int tid  = threadIdx.x;
    int warp = tid >> 5;
    int lane = tid & 31;
    int base = tid * 8;

    int el0 = g_eidx[base+0], el1 = g_eidx[base+1], el2 = g_eidx[base+2], el3 = g_eidx[base+3];
    int el4 = g_eidx[base+4], el5 = g_eidx[base+5], el6 = g_eidx[base+6], el7 = g_eidx[base+7];

    int q1 = (el0==el1);
    int q2 = (el0==el2)+(el1==el2);
    int q3 = (el0==el3)+(el1==el3)+(el2==el3);
    int q4 = (el0==el4)+(el1==el4)+(el2==el4)+(el3==el4);
    int q5 = (el0==el5)+(el1==el5)+(el2==el5)+(el3==el5)+(el4==el5);
    int q6 = (el0==el6)+(el1==el6)+(el2==el6)+(el3==el6)+(el4==el6)+(el5==el6);
    int q7 = (el0==el7)+(el1==el7)+(el2==el7)+(el3==el7)+(el4==el7)+(el5==el7)+(el6==el7);

#pragma unroll
    for (int e = 0; e < EE; e++) {
        int cnt = (el0==e)+(el1==e)+(el2==e)+(el3==e)+(el4==e)+(el5==e)+(el6==e)+(el7==e);
        int s = cnt;
#pragma unroll
        for (int off = 1; off < 32; off <<= 1) {
            int o = __shfl_up_sync(0xFFFFFFFFu, s, off);
            if (lane >= off) s += o;
        }
        sbase[tid][e] = s - cnt;
        if (lane == 31) wtot[warp][e] = s;
    }
    __syncthreads();

    if (warp == 0) {
#pragma unroll
        for (int e = 0; e < EE; e++) {
            int v = wtot[lane][e], s = v;
#pragma unroll
            for (int off = 1; off < 32; off <<= 1) {
                int o = __shfl_up_sync(0xFFFFFFFFu, s, off);
                if (lane >= off) s += o;
            }
            wtot[lane][e] = s - v;
            if (lane == 31) totals[e] = s;
        }
    }
    __syncthreads();

#pragma unroll
    for (int e = 0; e < EE; e++) sbase[tid][e] += wtot[warp][e];
    __syncthreads();

    {
        int g0 = sbase[tid][el0];
        int g1 = sbase[tid][el1] + q1;
        int g2 = sbase[tid][el2] + q2;
        int g3 = sbase[tid][el3] + q3;
        int g4 = sbase[tid][el4] + q4;
        int g5 = sbase[tid][el5] + q5;
        int g6 = sbase[tid][el6] + q6;
        int g7 = sbase[tid][el7] + q7;
        g_slot[base+0] = (g0 < CAP) ? g0 : -1;
        g_slot[base+1] = (g1 < CAP) ? g1 : -1;
        g_slot[base+2] = (g2 < CAP) ? g2 : -1;
        g_slot[base+3] = (g3 < CAP) ? g3 : -1;
        g_slot[base+4] = (g4 < CAP) ? g4 : -1;
        g_slot[base+5] = (g5 < CAP) ? g5 : -1;
        g_slot[base+6] = (g6 < CAP) ? g6 : -1;
        g_slot[base+7] = (g7 < CAP) ? g7 : -1;
        if (g0 < CAP) g_order[el0*CAP + g0] = base+0;
        if (g1 < CAP) g_order[el1*CAP + g1] = base+1;
        if (g2 < CAP) g_order[el2*CAP + g2] = base+2;
        if (g3 < CAP) g_order[el3*CAP + g3] = base+3;
        if (g4 < CAP) g_order[el4*CAP + g4] = base+4;
        if (g5 < CAP) g_order[el5*CAP + g5] = base+5;
        if (g6 < CAP) g_order[el6*CAP + g6] = base+6;
        if (g7 < CAP) g_order[el7*CAP + g7] = base+7;
    }

    if (tid < EE) {
        int c = totals[tid];
        g_cnt[tid] = (c < CAP) ? c : CAP;
    }

    if (tid == 0 && out_size > TT * DD) {
        float loss = 0.0f;
        float invT = 1.0f / (float)TT;
#pragma unroll
        for (int e = 0; e < EE; e++)
            loss += ((float)totals[e] * invT) * (g_gsum[e] * invT);
        d_out[TT * DD] = (float)EE * loss;
    }
}

// ======== tf32 mma.sync GEMMs: BM=160 single-wave grids, 4-stage cp.async ========
// BM=160, BN=128, BK=16, 256 threads = 8 warps (2m x 4n), warp tile 80x32 (5 m-frags).
// As [m][k] ld=20 (conflict-free frag loads), Bs [k][n] ld=136.
#define BM 160
#define MF 5                 // m-fragments per warp (80/16)
#define BN 128
#define BK 16
#define STAGES 4
#define AS_LD (BK + 4)       // 20 floats
#define BS_LD (BN + 8)       // 136 floats
#define A_SLOTS (BM * 4)     // 640 float4 slots per A stage

// dynamic smem layout (bytes)
#define SM_SROW   0
#define SM_A      1024
#define A_BUF_B   (BM * AS_LD * 4)          // 12800
#define SM_B      (SM_A + STAGES * A_BUF_B) // 1024 + 51200
#define B_BUF_B   (BK * BS_LD * 4)          // 8704
#define SMEM_TOT  (SM_B + STAGES * B_BUF_B) // 87040

__device__ __forceinline__ unsigned f2tf(float f) {
    unsigned r;
    asm("cvt.rna.tf32.f32 %0, %1;" : "=r"(r) : "f"(f));
    return r;
}

__device__ __forceinline__ void cpa16(unsigned dst, const float* src) {
    asm volatile("cp.async.ca.shared.global [%0], [%1], 16;" :: "r"(dst), "l"(src));
}
__device__ __forceinline__ void cpa16z(unsigned dst, const float* src) {
    asm volatile("cp.async.ca.shared.global [%0], [%1], 16, 0;" :: "r"(dst), "l"(src));
}
#define CP_COMMIT() asm volatile("cp.async.commit_group;")
#define CP_WAIT2()  asm volatile("cp.async.wait_group 2;")

#define MMA_TF32(d, av, bv) \
    asm volatile("mma.sync.aligned.m16n8k8.row.col.f32.tf32.tf32.f32 " \
                 "{%0,%1,%2,%3}, {%4,%5,%6,%7}, {%8,%9}, {%0,%1,%2,%3};" \
                 : "+f"(d[0]), "+f"(d[1]), "+f"(d[2]), "+f"(d[3]) \
                 : "r"(av[0]), "r"(av[1]), "r"(av[2]), "r"(av[3]), \
                   "r"(bv[0]), "r"(bv[1]))

__device__ __forceinline__ void tc_compute(const float (*Asb)[AS_LD],
                                           const float (*Bsb)[BS_LD],
                                           float (*acc)[4][4],
                                           int mwb, int nwb, int gid, int tg) {
#pragma unroll
    for (int ks = 0; ks < 2; ks++) {
        int k8 = ks * 8;
        unsigned af[MF][4];
#pragma unroll
        for (int mi = 0; mi < MF; mi++) {
            int r0 = mwb + mi * 16 + gid;
            af[mi][0] = f2tf(Asb[r0    ][k8 + tg    ]);
            af[mi][1] = f2tf(Asb[r0 + 8][k8 + tg    ]);
            af[mi][2] = f2tf(Asb[r0    ][k8 + tg + 4]);
            af[mi][3] = f2tf(Asb[r0 + 8][k8 + tg + 4]);
        }
        unsigned bf[4][2];
#pragma unroll
        for (int ni = 0; ni < 4; ni++) {
            int c0 = nwb + ni * 8 + gid;
            bf[ni][0] = f2tf(Bsb[k8 + tg    ][c0]);
            bf[ni][1] = f2tf(Bsb[k8 + tg + 4][c0]);
        }
#pragma unroll
        for (int mi = 0; mi < MF; mi++)
#pragma unroll
            for (int ni = 0; ni < 4; ni++)
                MMA_TF32(acc[mi][ni], af[mi], bf[ni]);
    }
}

// ---------------- GEMM1: h_chunk = relu(gather(x) @ w1[:,:,chunk] + b1) ----------
__global__ __launch_bounds__(256)
void gemm1_kernel(const float* __restrict__ x, const float* __restrict__ w1,
                  const float* __restrict__ b1, int chunk) {
    extern __shared__ char smem[];
    int e  = blockIdx.z;
    int m0 = blockIdx.y * BM;
    int n0 = blockIdx.x * BN;
    const float* Bp   = w1 + (size_t)e * DD * FF + (size_t)chunk * FCH;
    const float* bias = b1 + (size_t)e * FF + (size_t)chunk * FCH;
    float* C = g_h + (size_t)e * CAP * FCH;
    int cnt = g_cnt[e];

    int* srow = (int*)(smem + SM_SROW);
    int tid = threadIdx.x;
    if (tid < BM) {
        int m = m0 + tid;
        srow[tid] = (m < cnt) ? g_order[e * CAP + m] : -1;
    }
    __syncthreads();

    int wid = tid >> 5, lane = tid & 31;
    int gid = lane >> 2, tg = lane & 3;
    int mwb = (wid >> 2) * 80;
    int nwb = (wid & 3) * 32;

    int bk = tid >> 4;
    int bc = (tid & 15) * 8;
    const float* brow = Bp + (size_t)bk * FF + n0 + bc;

    unsigned aBase = (unsigned)__cvta_generic_to_shared(smem + SM_A);
    unsigned bBase = (unsigned)__cvta_generic_to_shared(smem + SM_B);
    unsigned bOff  = ((unsigned)(bk * BS_LD + bc)) * 4u;

    float acc[MF][4][4];
#pragma unroll
    for (int mi = 0; mi < MF; mi++)
#pragma unroll
        for (int ni = 0; ni < 4; ni++)
#pragma unroll
            for (int i = 0; i < 4; i++) acc[mi][ni][i] = 0.0f;

    const int nit = DD / BK;   // 64
    // prologue: stages 0..2
#pragma unroll
    for (int s = 0; s < STAGES - 1; s++) {
        int k0 = s * BK;
        unsigned aSt = aBase + (unsigned)s * A_BUF_B;
        for (int slot = tid; slot < A_SLOTS; slot += 256) {
            int row = slot >> 2, kq = (slot & 3) * 4;
            unsigned ad = aSt + ((unsigned)(row * AS_LD + kq)) * 4u;
            int gt = srow[row];
            if (gt >= 0) cpa16(ad, x + (size_t)gt * DD + k0 + kq);
            else         cpa16z(ad, x);
        }
        unsigned bd = bBase + (unsigned)s * B_BUF_B + bOff;
        const float* bs = brow + (size_t)k0 * FF;
        cpa16(bd, bs); cpa16(bd + 16, bs + 4);
        CP_COMMIT();
    }

    for (int t = 0; t < nit; t++) {
        CP_WAIT2();
        __syncthreads();
        int pf = t + STAGES - 1;
        if (pf < nit) {
            int nb = pf & (STAGES - 1);
            int k0 = pf * BK;
            unsigned aSt = aBase + (unsigned)nb * A_BUF_B;
            for (int slot = tid; slot < A_SLOTS; slot += 256) {
                int row = slot >> 2, kq = (slot & 3) * 4;
                unsigned ad = aSt + ((unsigned)(row * AS_LD + kq)) * 4u;
                int gt = srow[row];
                if (gt >= 0) cpa16(ad, x + (size_t)gt * DD + k0 + kq);
                else         cpa16z(ad, x);
            }
            unsigned bd = bBase + (unsigned)nb * B_BUF_B + bOff;
            const float* bs = brow + (size_t)k0 * FF;
            cpa16(bd, bs); cpa16(bd + 16, bs + 4);
        }
        CP_COMMIT();   // every iter, keeps wait_group-2 invariant through the tail
        int buf = t & (STAGES - 1);
        tc_compute((const float(*)[AS_LD])(smem + SM_A + buf * A_BUF_B),
                   (const float(*)[BS_LD])(smem + SM_B + buf * B_BUF_B),
                   acc, mwb, nwb, gid, tg);
    }

    // epilogue: + bias, relu -> g_h (rows always < CAP since 2*BM == CAP)
#pragma unroll
    for (int mi = 0; mi < MF; mi++) {
#pragma unroll
        for (int i = 0; i < 2; i++) {
            int row = m0 + mwb + mi * 16 + gid + i * 8;
#pragma unroll
            for (int ni = 0; ni < 4; ni++) {
                int col = n0 + nwb + ni * 8 + tg * 2;
                float2 o;
                o.x = fmaxf(acc[mi][ni][i*2+0] + bias[col],     0.0f);
                o.y = fmaxf(acc[mi][ni][i*2+1] + bias[col + 1], 0.0f);
                *(float2*)(C + (size_t)row * FCH + col) = o;
            }
        }
    }
}

// ---------------- GEMM2: out[token] (+)= h_chunk @ w2[chunk] (+ b2 on wave 0) ----
__global__ __launch_bounds__(256)
void gemm2_kernel(const float* __restrict__ w2, const float* __restrict__ b2,
                  float* __restrict__ out, int chunk, int accflag) {
    extern __shared__ char smem[];
    int e  = blockIdx.z;
    int m0 = blockIdx.y * BM;
    int n0 = blockIdx.x * BN;
    const float* Ap   = g_h + (size_t)e * CAP * FCH;
    const float* Bp   = w2 + (size_t)e * FF * DD + (size_t)chunk * FCH * DD;
    const float* bias = b2 + (size_t)e * DD;
    int cnt = g_cnt[e];

    int* srow = (int*)(smem + SM_SROW);
    int tid = threadIdx.x;
    if (tid < BM) {
        int m = m0 + tid;
        srow[tid] = (m < cnt) ? g_order[e * CAP + m] : -1;
    }
    __syncthreads();

    int wid = tid >> 5, lane = tid & 31;
    int gid = lane >> 2, tg = lane & 3;
    int mwb = (wid >> 2) * 80;
    int nwb = (wid & 3) * 32;

    int bk = tid >> 4;
    int bc = (tid & 15) * 8;
    const float* brow = Bp + (size_t)bk * DD + n0 + bc;
    const float* Arow0 = Ap + (size_t)m0 * FCH;   // rows m0..m0+159 all < CAP

    unsigned aBase = (unsigned)__cvta_generic_to_shared(smem + SM_A);
    unsigned bBase = (unsigned)__cvta_generic_to_shared(smem + SM_B);
    unsigned bOff  = ((unsigned)(bk * BS_LD + bc)) * 4u;

    float acc[MF][4][4];
#pragma unroll
    for (int mi = 0; mi < MF; mi++)
#pragma unroll
        for (int ni = 0; ni < 4; ni++)
#pragma unroll
            for (int i = 0; i < 4; i++) acc[mi][ni][i] = 0.0f;

    const int nit = FCH / BK;  // 64
#pragma unroll
    for (int s = 0; s < STAGES - 1; s++) {
        int k0 = s * BK;
        unsigned aSt = aBase + (unsigned)s * A_BUF_B;
        for (int slot = tid; slot < A_SLOTS; slot += 256) {
            int row = slot >> 2, kq = (slot & 3) * 4;
            unsigned ad = aSt + ((unsigned)(row * AS_LD + kq)) * 4u;
            cpa16(ad, Arow0 + (size_t)row * FCH + k0 + kq);
        }
        unsigned bd = bBase + (unsigned)s * B_BUF_B + bOff;
        const float* bs = brow + (size_t)k0 * DD;
        cpa16(bd, bs); cpa16(bd + 16, bs + 4);
        CP_COMMIT();
    }

    for (int t = 0; t < nit; t++) {
        CP_WAIT2();
        __syncthreads();
        int pf = t + STAGES - 1;
        if (pf < nit) {
            int nb = pf & (STAGES - 1);
            int k0 = pf * BK;
            unsigned aSt = aBase + (unsigned)nb * A_BUF_B;
            for (int slot = tid; slot < A_SLOTS; slot += 256) {
                int row = slot >> 2, kq = (slot & 3) * 4;
                unsigned ad = aSt + ((unsigned)(row * AS_LD + kq)) * 4u;
                cpa16(ad, Arow0 + (size_t)row * FCH + k0 + kq);
            }
            unsigned bd = bBase + (unsigned)nb * B_BUF_B + bOff;
            const float* bs = brow + (size_t)k0 * DD;
            cpa16(bd, bs); cpa16(bd + 16, bs + 4);
        }
        CP_COMMIT();
        int buf = t & (STAGES - 1);
        tc_compute((const float(*)[AS_LD])(smem + SM_A + buf * A_BUF_B),
                   (const float(*)[BS_LD])(smem + SM_B + buf * B_BUF_B),
                   acc, mwb, nwb, gid, tg);
    }

    // epilogue: scatter to out (RMW on later waves; bias on wave 0)
#pragma unroll
    for (int mi = 0; mi < MF; mi++) {
#pragma unroll
        for (int i = 0; i < 2; i++) {
            int lr = mwb + mi * 16 + gid + i * 8;
            int t  = srow[lr];
            if (t >= 0) {
#pragma unroll
                for (int ni = 0; ni < 4; ni++) {
                    int col = n0 + nwb + ni * 8 + tg * 2;
                    float2* cp = (float2*)(out + (size_t)t * DD + col);
                    float2 o;
                    if (accflag) {
                        o = *cp;
                        o.x += acc[mi][ni][i*2+0];
                        o.y += acc[mi][ni][i*2+1];
                    } else {
                        o.x = acc[mi][ni][i*2+0] + bias[col];
                        o.y = acc[mi][ni][i*2+1] + bias[col + 1];
                    }
                    *cp = o;
                }
            }
        }
    }
}

// ---------------- eager-load + smem attr (default-priority ctor) ----------------
namespace {
struct ModulePreloader {
    ModulePreloader() {
        setenv("CUDA_MODULE_LOADING", "EAGER", 1);
        void* p = nullptr;
        (void)cudaGetSymbolAddress(&p, g_h);
        (void)cudaGetSymbolAddress(&p, g_eidx);
        (void)cudaGetSymbolAddress(&p, g_slot);
        (void)cudaGetSymbolAddress(&p, g_order);
        (void)cudaGetSymbolAddress(&p, g_cnt);
        (void)cudaGetSymbolAddress(&p, g_gsum);
        cudaFuncAttributes a;
        (void)cudaFuncGetAttributes(&a, (const void*)router_kernel);
        (void)cudaFuncGetAttributes(&a, (const void*)scan_kernel);
        (void)cudaFuncGetAttributes(&a, (const void*)gemm1_kernel);
        (void)cudaFuncGetAttributes(&a, (const void*)gemm2_kernel);
        (void)cudaFuncGetAttributes(&a, (const void*)zero_out_kernel);
        (void)cudaFuncGetAttributes(&a, (const void*)init_kernel);
        (void)cudaFuncSetAttribute((const void*)gemm1_kernel,
                                   cudaFuncAttributeMaxDynamicSharedMemorySize, SMEM_TOT);
        (void)cudaFuncSetAttribute((const void*)gemm2_kernel,
                                   cudaFuncAttributeMaxDynamicSharedMemorySize, SMEM_TOT);
    }
};
ModulePreloader g_module_preloader;
}

// ---------------- launch ----------------
extern "C" void kernel_launch(void* const* d_in, const int* in_sizes, int n_in,
                              void* d_out, int out_size) {
    const float* x   = (const float*)d_in[0];
    const float* wr  = (const float*)d_in[1];
    const float* w1  = (const float*)d_in[2];
    const float* b1  = (const float*)d_in[3];
    const float* w2  = (const float*)d_in[4];
    const float* b2  = (const float*)d_in[5];
    float* out = (float*)d_out;

    (void)cudaFuncSetAttribute((const void*)gemm1_kernel,
                               cudaFuncAttributeMaxDynamicSharedMemorySize, SMEM_TOT);
    (void)cudaFuncSetAttribute((const void*)gemm2_kernel,
                               cudaFuncAttributeMaxDynamicSharedMemorySize, SMEM_TOT);

    init_kernel<<<1, 32>>>();
    router_kernel<<<TT / 8, 256>>>(x, wr);
    zero_out_kernel<<<(TT * DD / 4) / 256, 256>>>(out);
    scan_kernel<<<1, 1024>>>(out, out_size);

    dim3 grid1(FCH / BN, CAP / BM, EE);   // 8 x 2 x 8 = 128 CTAs (single wave)
    dim3 grid2(DD  / BN, CAP / BM, EE);   // 8 x 2 x 8 = 128 CTAs (single wave)
    for (int c = 0; c < NWAVE; c++) {
        gemm1_kernel<<<grid1, 256, SMEM_TOT>>>(x, w1, b1, c);
        gemm2_kernel<<<grid2, 256, SMEM_TOT>>>(w2, b2, out, c, c > 0 ? 1 : 0);
    }
}

// round 15
// speedup vs baseline: 4.2219x; 1.1157x over previous
#include <cuda_runtime.h>
#include <cuda_bf16.h>
#include <math.h>
#include <stdlib.h>
#include <stdint.h>

// Problem constants
#define BB 4
#define SS 2048
#define DD 1024
#define FF 4096
#define EE 8
#define TT (BB*SS)          // 8192 tokens
#define CAP 320             // int(2048/8 * 1.25)

// ---------------- scratch (~42 MB; no allocations allowed) ----------------
__device__ float g_h[EE * CAP * FF];    // hidden activations [E, CAP, F]
__device__ int   g_eidx[TT];
__device__ int   g_slot[TT];
__device__ int   g_order[EE * CAP];
__device__ int   g_cnt[EE];
__device__ float g_gsum[EE];

// ---------------- zero out + per-replay accumulators ----------------
__global__ void zero_out_kernel(float* __restrict__ out) {
    size_t i = (size_t)blockIdx.x * 256 + threadIdx.x;
    ((float4*)out)[i] = make_float4(0.f, 0.f, 0.f, 0.f);
    if (blockIdx.x == 0 && threadIdx.x < EE) g_gsum[threadIdx.x] = 0.0f;
}

// ---------------- router ----------------
__global__ void router_kernel(const float* __restrict__ x,
                              const float* __restrict__ wr) {
    __shared__ float sg[EE];
    int tid  = threadIdx.x;
    int warp = tid >> 5;
    int lane = tid & 31;
    if (tid < EE) sg[tid] = 0.0f;
    __syncthreads();

    int t = blockIdx.x * 8 + warp;
    const float* xr = x + (size_t)t * DD;

    float p0=0.f,p1=0.f,p2=0.f,p3=0.f,p4=0.f,p5=0.f,p6=0.f,p7=0.f;
    for (int k = lane; k < DD; k += 32) {
        float xv = xr[k];
        const float4* w4 = (const float4*)(wr + (size_t)k * EE);
        float4 w0 = w4[0], w1 = w4[1];
        p0 = fmaf(xv, w0.x, p0); p1 = fmaf(xv, w0.y, p1);
        p2 = fmaf(xv, w0.z, p2); p3 = fmaf(xv, w0.w, p3);
        p4 = fmaf(xv, w1.x, p4); p5 = fmaf(xv, w1.y, p5);
        p6 = fmaf(xv, w1.z, p6); p7 = fmaf(xv, w1.w, p7);
    }
#pragma unroll
    for (int off = 16; off > 0; off >>= 1) {
        p0 += __shfl_xor_sync(0xFFFFFFFFu, p0, off);
        p1 += __shfl_xor_sync(0xFFFFFFFFu, p1, off);
        p2 += __shfl_xor_sync(0xFFFFFFFFu, p2, off);
        p3 += __shfl_xor_sync(0xFFFFFFFFu, p3, off);
        p4 += __shfl_xor_sync(0xFFFFFFFFu, p4, off);
        p5 += __shfl_xor_sync(0xFFFFFFFFu, p5, off);
        p6 += __shfl_xor_sync(0xFFFFFFFFu, p6, off);
        p7 += __shfl_xor_sync(0xFFFFFFFFu, p7, off);
    }

    if (lane == 0) {
        int best = 0; float bv = p0;
        if (p1 > bv) { bv = p1; best = 1; }
        if (p2 > bv) { bv = p2; best = 2; }
        if (p3 > bv) { bv = p3; best = 3; }
        if (p4 > bv) { bv = p4; best = 4; }
        if (p5 > bv) { bv = p5; best = 5; }
        if (p6 > bv) { bv = p6; best = 6; }
        if (p7 > bv) { bv = p7; best = 7; }
        g_eidx[t] = best;
        float m = bv;
        float e0 = __expf(p0 - m), e1 = __expf(p1 - m), e2 = __expf(p2 - m), e3 = __expf(p3 - m);
        float e4 = __expf(p4 - m), e5 = __expf(p5 - m), e6 = __expf(p6 - m), e7 = __expf(p7 - m);
        float inv = 1.0f / (e0+e1+e2+e3+e4+e5+e6+e7);
        atomicAdd(&sg[0], e0 * inv); atomicAdd(&sg[1], e1 * inv);
        atomicAdd(&sg[2], e2 * inv); atomicAdd(&sg[3], e3 * inv);
        atomicAdd(&sg[4], e4 * inv); atomicAdd(&sg[5], e5 * inv);
        atomicAdd(&sg[6], e6 * inv); atomicAdd(&sg[7], e7 * inv);
    }
    __syncthreads();
    if (tid < EE) atomicAdd(&g_gsum[tid], sg[tid]);
}

// ---------------- scan ----------------
__global__ void scan_kernel(float* __restrict__ d_out, int out_size) {
    __shared__ int wtot[32][EE];
    __shared__ int totals[EE];
    __shared__ int sbase[1024][EE];

    int tid  = threadIdx.x;
    int warp = tid >> 5;
    int lane = tid & 31;
    int base = tid * 8;

    int el0 = g_eidx[base+0], el1 = g_eidx[base+1], el2 = g_eidx[base+2], el3 = g_eidx[base+3];
    int el4 = g_eidx[base+4], el5 = g_eidx[base+5], el6 = g_eidx[base+6], el7 = g_eidx[base+7];

    int q1 = (el0==el1);
    int q2 = (el0==el2)+(el1==el2);
    int q3 = (el0==el3)+(el1==el3)+(el2==el3);
    int q4 = (el0==el4)+(el1==el4)+(el2==el4)+(el3==el4);
    int q5 = (el0==el5)+(el1==el5)+(el2==el5)+(el3==el5)+(el4==el5);
    int q6 = (el0==el6)+(el1==el6)+(el2==el6)+(el3==el6)+(el4==el6)+(el5==el6);
    int q7 = (el0==el7)+(el1==el7)+(el2==el7)+(el3==el7)+(el4==el7)+(el5==el7)+(el6==el7);

#pragma unroll
    for (int e = 0; e < EE; e++) {
        int cnt = (el0==e)+(el1==e)+(el2==e)+(el3==e)+(el4==e)+(el5==e)+(el6==e)+(el7==e);
        int s = cnt;
#pragma unroll
        for (int off = 1; off < 32; off <<= 1) {
            int o = __shfl_up_sync(0xFFFFFFFFu, s, off);
            if (lane >= off) s += o;
        }
        sbase[tid][e] = s - cnt;
        if (lane == 31) wtot[warp][e] = s;
    }
    __syncthreads();

    if (warp == 0) {
#pragma unroll
        for (int e = 0; e < EE; e++) {
            int v = wtot[lane][e], s = v;
#pragma unroll
            for (int off = 1; off < 32; off <<= 1) {
                int o = __shfl_up_sync(0xFFFFFFFFu, s, off);
                if (lane >= off) s += o;
            }
            wtot[lane][e] = s - v;
            if (lane == 31) totals[e] = s;
        }
    }
    __syncthreads();

#pragma unroll
    for (int e = 0; e < EE; e++) sbase[tid][e] += wtot[warp][e];
    __syncthreads();

    {
        int g0 = sbase[tid][el0];
        int g1 = sbase[tid][el1] + q1;
        int g2 = sbase[tid][el2] + q2;
        int g3 = sbase[tid][el3] + q3;
        int g4 = sbase[tid][el4] + q4;
        int g5 = sbase[tid][el5] + q5;
        int g6 = sbase[tid][el6] + q6;
        int g7 = sbase[tid][el7] + q7;
        g_slot[base+0] = (g0 < CAP) ? g0 : -1;
        g_slot[base+1] = (g1 < CAP) ? g1 : -1;
        g_slot[base+2] = (g2 < CAP) ? g2 : -1;
        g_slot[base+3] = (g3 < CAP) ? g3 : -1;
        g_slot[base+4] = (g4 < CAP) ? g4 : -1;
        g_slot[base+5] = (g5 < CAP) ? g5 : -1;
        g_slot[base+6] = (g6 < CAP) ? g6 : -1;
        g_slot[base+7] = (g7 < CAP) ? g7 : -1;
        if (g0 < CAP) g_order[el0*CAP + g0] = base+0;
        if (g1 < CAP) g_order[el1*CAP + g1] = base+1;
        if (g2 < CAP) g_order[el2*CAP + g2] = base+2;
        if (g3 < CAP) g_order[el3*CAP + g3] = base+3;
        if (g4 < CAP) g_order[el4*CAP + g4] = base+4;
        if (g5 < CAP) g_order[el5*CAP + g5] = base+5;
        if (g6 < CAP) g_order[el6*CAP + g6] = base+6;
        if (g7 < CAP) g_order[el7*CAP + g7] = base+7;
    }

    if (tid < EE) {
        int c = totals[tid];
        g_cnt[tid] = (c < CAP) ? c : CAP;
    }

    if (tid == 0 && out_size > TT * DD) {
        float loss = 0.0f;
        float invT = 1.0f / (float)TT;
#pragma unroll
        for (int e = 0; e < EE; e++)
            loss += ((float)totals[e] * invT) * (g_gsum[e] * invT);
        d_out[TT * DD] = (float)EE * loss;
    }
}

// ======== tf32 mma.sync GEMMs: BM=160, 4-stage cp.async, single launch each ========
#define BM 160
#define MF 5                 // m-fragments per warp (80/16)
#define BN 128
#define BK 16
#define STAGES 4
#define AS_LD (BK + 4)       // 20 floats
#define BS_LD (BN + 8)       // 136 floats
#define A_SLOTS (BM * 4)     // 640 float4 slots per A stage

// dynamic smem layout (bytes)
#define SM_SROW   0
#define SM_A      1024
#define A_BUF_B   (BM * AS_LD * 4)          // 12800
#define SM_B      (SM_A + STAGES * A_BUF_B) // 1024 + 51200
#define B_BUF_B   (BK * BS_LD * 4)          // 8704
#define SMEM_TOT  (SM_B + STAGES * B_BUF_B) // 87040

__device__ __forceinline__ unsigned f2tf(float f) {
    unsigned r;
    asm("cvt.rna.tf32.f32 %0, %1;" : "=r"(r) : "f"(f));
    return r;
}

__device__ __forceinline__ void cpa16(unsigned dst, const float* src) {
    asm volatile("cp.async.ca.shared.global [%0], [%1], 16;" :: "r"(dst), "l"(src));
}
__device__ __forceinline__ void cpa16z(unsigned dst, const float* src) {
    asm volatile("cp.async.ca.shared.global [%0], [%1], 16, 0;" :: "r"(dst), "l"(src));
}
#define CP_COMMIT() asm volatile("cp.async.commit_group;")
#define CP_WAIT2()  asm volatile("cp.async.wait_group 2;")

#define MMA_TF32(d, av, bv) \
    asm volatile("mma.sync.aligned.m16n8k8.row.col.f32.tf32.tf32.f32 " \
                 "{%0,%1,%2,%3}, {%4,%5,%6,%7}, {%8,%9}, {%0,%1,%2,%3};" \
                 : "+f"(d[0]), "+f"(d[1]), "+f"(d[2]), "+f"(d[3]) \
                 : "r"(av[0]), "r"(av[1]), "r"(av[2]), "r"(av[3]), \
                   "r"(bv[0]), "r"(bv[1]))

__device__ __forceinline__ void tc_compute(const float (*Asb)[AS_LD],
                                           const float (*Bsb)[BS_LD],
                                           float (*acc)[4][4],
                                           int mwb, int nwb, int gid, int tg) {
#pragma unroll
    for (int ks = 0; ks < 2; ks++) {
        int k8 = ks * 8;
        unsigned af[MF][4];
#pragma unroll
        for (int mi = 0; mi < MF; mi++) {
            int r0 = mwb + mi * 16 + gid;
            af[mi][0] = f2tf(Asb[r0    ][k8 + tg    ]);
            af[mi][1] = f2tf(Asb[r0 + 8][k8 + tg    ]);
            af[mi][2] = f2tf(Asb[r0    ][k8 + tg + 4]);
            af[mi][3] = f2tf(Asb[r0 + 8][k8 + tg + 4]);
        }
        unsigned bf[4][2];
#pragma unroll
        for (int ni = 0; ni < 4; ni++) {
            int c0 = nwb + ni * 8 + gid;
            bf[ni][0] = f2tf(Bsb[k8 + tg    ][c0]);
            bf[ni][1] = f2tf(Bsb[k8 + tg + 4][c0]);
        }
#pragma unroll
        for (int mi = 0; mi < MF; mi++)
#pragma unroll
            for (int ni = 0; ni < 4; ni++)
                MMA_TF32(acc[mi][ni], af[mi], bf[ni]);
    }
}

// ---------------- GEMM1: h = relu(gather(x) @ w1 + b1)   [single launch, all F] ----
__global__ __launch_bounds__(256)
void gemm1_kernel(const float* __restrict__ x, const float* __restrict__ w1,
                  const float* __restrict__ b1) {
    extern __shared__ char smem[];
    int e  = blockIdx.z;
    int m0 = blockIdx.y * BM;
    int n0 = blockIdx.x * BN;
    const float* Bp   = w1 + (size_t)e * DD * FF;        // row k stride FF
    const float* bias = b1 + (size_t)e * FF;
    float* C = g_h + (size_t)e * CAP * FF;
    int cnt = g_cnt[e];

    int* srow = (int*)(smem + SM_SROW);
    int tid = threadIdx.x;
    if (tid < BM) {
        int m = m0 + tid;
        srow[tid] = (m < cnt) ? g_order[e * CAP + m] : -1;
    }
    __syncthreads();

    int wid = tid >> 5, lane = tid & 31;
    int gid = lane >> 2, tg = lane & 3;
    int mwb = (wid >> 2) * 80;
    int nwb = (wid & 3) * 32;

    int bk = tid >> 4;
    int bc = (tid & 15) * 8;
    const float* brow = Bp + (size_t)bk * FF + n0 + bc;

    unsigned aBase = (unsigned)__cvta_generic_to_shared(smem + SM_A);
    unsigned bBase = (unsigned)__cvta_generic_to_shared(smem + SM_B);
    unsigned bOff  = ((unsigned)(bk * BS_LD + bc)) * 4u;

    float acc[MF][4][4];
#pragma unroll
    for (int mi = 0; mi < MF; mi++)
#pragma unroll
        for (int ni = 0; ni < 4; ni++)
#pragma unroll
            for (int i = 0; i < 4; i++) acc[mi][ni][i] = 0.0f;

    const int nit = DD / BK;   // 64
#pragma unroll
    for (int s = 0; s < STAGES - 1; s++) {
        int k0 = s * BK;
        unsigned aSt = aBase + (unsigned)s * A_BUF_B;
        for (int slot = tid; slot < A_SLOTS; slot += 256) {
            int row = slot >> 2, kq = (slot & 3) * 4;
            unsigned ad = aSt + ((unsigned)(row * AS_LD + kq)) * 4u;
            int gt = srow[row];
            if (gt >= 0) cpa16(ad, x + (size_t)gt * DD + k0 + kq);
            else         cpa16z(ad, x);
        }
        unsigned bd = bBase + (unsigned)s * B_BUF_B + bOff;
        const float* bs = brow + (size_t)k0 * FF;
        cpa16(bd, bs); cpa16(bd + 16, bs + 4);
        CP_COMMIT();
    }

    for (int t = 0; t < nit; t++) {
        CP_WAIT2();
        __syncthreads();
        int pf = t + STAGES - 1;
        if (pf < nit) {
            int nb = pf & (STAGES - 1);
            int k0 = pf * BK;
            unsigned aSt = aBase + (unsigned)nb * A_BUF_B;
            for (int slot = tid; slot < A_SLOTS; slot += 256) {
                int row = slot >> 2, kq = (slot & 3) * 4;
                unsigned ad = aSt + ((unsigned)(row * AS_LD + kq)) * 4u;
                int gt = srow[row];
                if (gt >= 0) cpa16(ad, x + (size_t)gt * DD + k0 + kq);
                else         cpa16z(ad, x);
            }
            unsigned bd = bBase + (unsigned)nb * B_BUF_B + bOff;
            const float* bs = brow + (size_t)k0 * FF;
            cpa16(bd, bs); cpa16(bd + 16, bs + 4);
        }
        CP_COMMIT();
        int buf = t & (STAGES - 1);
        tc_compute((const float(*)[AS_LD])(smem + SM_A + buf * A_BUF_B),
                   (const float(*)[BS_LD])(smem + SM_B + buf * B_BUF_B),
                   acc, mwb, nwb, gid, tg);
    }

    // epilogue: + bias, relu -> g_h (rows always < CAP since 2*BM == CAP)
#pragma unroll
    for (int mi = 0; mi < MF; mi++) {
#pragma unroll
        for (int i = 0; i < 2; i++) {
            int row = m0 + mwb + mi * 16 + gid + i * 8;
#pragma unroll
            for (int ni = 0; ni < 4; ni++) {
                int col = n0 + nwb + ni * 8 + tg * 2;
                float2 o;
                o.x = fmaxf(acc[mi][ni][i*2+0] + bias[col],     0.0f);
                o.y = fmaxf(acc[mi][ni][i*2+1] + bias[col + 1], 0.0f);
                *(float2*)(C + (size_t)row * FF + col) = o;
            }
        }
    }
}

// ---------------- GEMM2: out[token] = h @ w2 + b2   [single launch, K=4096] ----
__global__ __launch_bounds__(256)
void gemm2_kernel(const float* __restrict__ w2, const float* __restrict__ b2,
                  float* __restrict__ out) {
    extern __shared__ char smem[];
    int e  = blockIdx.z;
    int m0 = blockIdx.y * BM;
    int n0 = blockIdx.x * BN;
    const float* Ap   = g_h + (size_t)e * CAP * FF;
    const float* Bp   = w2 + (size_t)e * FF * DD;
    const float* bias = b2 + (size_t)e * DD;
    int cnt = g_cnt[e];

    int* srow = (int*)(smem + SM_SROW);
    int tid = threadIdx.x;
    if (tid < BM) {
        int m = m0 + tid;
        srow[tid] = (m < cnt) ? g_order[e * CAP + m] : -1;
    }
    __syncthreads();

    int wid = tid >> 5, lane = tid & 31;
    int gid = lane >> 2, tg = lane & 3;
    int mwb = (wid >> 2) * 80;
    int nwb = (wid & 3) * 32;

    int bk = tid >> 4;
    int bc = (tid & 15) * 8;
    const float* brow  = Bp + (size_t)bk * DD + n0 + bc;
    const float* Arow0 = Ap + (size_t)m0 * FF;     // rows m0..m0+159 all < CAP

    unsigned aBase = (unsigned)__cvta_generic_to_shared(smem + SM_A);
    unsigned bBase = (unsigned)__cvta_generic_to_shared(smem + SM_B);
    unsigned bOff  = ((unsigned)(bk * BS_LD + bc)) * 4u;

    float acc[MF][4][4];
#pragma unroll
    for (int mi = 0; mi < MF; mi++)
#pragma unroll
        for (int ni = 0; ni < 4; ni++)
#pragma unroll
            for (int i = 0; i < 4; i++) acc[mi][ni][i] = 0.0f;

    const int nit = FF / BK;   // 256
#pragma unroll
    for (int s = 0; s < STAGES - 1; s++) {
        int k0 = s * BK;
        unsigned aSt = aBase + (unsigned)s * A_BUF_B;
        for (int slot = tid; slot < A_SLOTS; slot += 256) {
            int row = slot >> 2, kq = (slot & 3) * 4;
            unsigned ad = aSt + ((unsigned)(row * AS_LD + kq)) * 4u;
            cpa16(ad, Arow0 + (size_t)row * FF + k0 + kq);
        }
        unsigned bd = bBase + (unsigned)s * B_BUF_B + bOff;
        const float* bs = brow + (size_t)k0 * DD;
        cpa16(bd, bs); cpa16(bd + 16, bs + 4);
        CP_COMMIT();
    }

    for (int t = 0; t < nit; t++) {
        CP_WAIT2();
        __syncthreads();
        int pf = t + STAGES - 1;
        if (pf < nit) {
            int nb = pf & (STAGES - 1);
            int k0 = pf * BK;
            unsigned aSt = aBase + (unsigned)nb * A_BUF_B;
            for (int slot = tid; slot < A_SLOTS; slot += 256) {
                int row = slot >> 2, kq = (slot & 3) * 4;
                unsigned ad = aSt + ((unsigned)(row * AS_LD + kq)) * 4u;
                cpa16(ad, Arow0 + (size_t)row * FF + k0 + kq);
            }
            unsigned bd = bBase + (unsigned)nb * B_BUF_B + bOff;
            const float* bs = brow + (size_t)k0 * DD;
            cpa16(bd, bs); cpa16(bd + 16, bs + 4);
        }
        CP_COMMIT();
        int buf = t & (STAGES - 1);
        tc_compute((const float(*)[AS_LD])(smem + SM_A + buf * A_BUF_B),
                   (const float(*)[BS_LD])(smem + SM_B + buf * B_BUF_B),
                   acc, mwb, nwb, gid, tg);
    }

    // epilogue: scatter to out with bias (single pass over K, no RMW)
#pragma unroll
    for (int mi = 0; mi < MF; mi++) {
#pragma unroll
        for (int i = 0; i < 2; i++) {
            int lr = mwb + mi * 16 + gid + i * 8;
            int t  = srow[lr];
            if (t >= 0) {
#pragma unroll
                for (int ni = 0; ni < 4; ni++) {
                    int col = n0 + nwb + ni * 8 + tg * 2;
                    float2 o;
                    o.x = acc[mi][ni][i*2+0] + bias[col];
                    o.y = acc[mi][ni][i*2+1] + bias[col + 1];
                    *(float2*)(out + (size_t)t * DD + col) = o;
                }
            }
        }
    }
}

// ---------------- eager-load + smem attr (default-priority ctor) ----------------
namespace {
struct ModulePreloader {
    ModulePreloader() {
        setenv("CUDA_MODULE_LOADING", "EAGER", 1);
        void* p = nullptr;
        (void)cudaGetSymbolAddress(&p, g_h);
        (void)cudaGetSymbolAddress(&p, g_eidx);
        (void)cudaGetSymbolAddress(&p, g_slot);
        (void)cudaGetSymbolAddress(&p, g_order);
        (void)cudaGetSymbolAddress(&p, g_cnt);
        (void)cudaGetSymbolAddress(&p, g_gsum);
        cudaFuncAttributes a;
        (void)cudaFuncGetAttributes(&a, (const void*)router_kernel);
        (void)cudaFuncGetAttributes(&a, (const void*)scan_kernel);
        (void)cudaFuncGetAttributes(&a, (const void*)gemm1_kernel);
        (void)cudaFuncGetAttributes(&a, (const void*)gemm2_kernel);
        (void)cudaFuncGetAttributes(&a, (const void*)zero_out_kernel);
        (void)cudaFuncSetAttribute((const void*)gemm1_kernel,
                                   cudaFuncAttributeMaxDynamicSharedMemorySize, SMEM_TOT);
        (void)cudaFuncSetAttribute((const void*)gemm2_kernel,
                                   cudaFuncAttributeMaxDynamicSharedMemorySize, SMEM_TOT);
    }
};
ModulePreloader g_module_preloader;
}

// ---------------- launch ----------------
extern "C" void kernel_launch(void* const* d_in, const int* in_sizes, int n_in,
                              void* d_out, int out_size) {
    const float* x   = (const float*)d_in[0];
    const float* wr  = (const float*)d_in[1];
    const float* w1  = (const float*)d_in[2];
    const float* b1  = (const float*)d_in[3];
    const float* w2  = (const float*)d_in[4];
    const float* b2  = (const float*)d_in[5];
    float* out = (float*)d_out;

    (void)cudaFuncSetAttribute((const void*)gemm1_kernel,
                               cudaFuncAttributeMaxDynamicSharedMemorySize, SMEM_TOT);
    (void)cudaFuncSetAttribute((const void*)gemm2_kernel,
                               cudaFuncAttributeMaxDynamicSharedMemorySize, SMEM_TOT);

    zero_out_kernel<<<(TT * DD / 4) / 256, 256>>>(out);   // also zeroes g_gsum
    router_kernel<<<TT / 8, 256>>>(x, wr);
    scan_kernel<<<1, 1024>>>(out, out_size);

    dim3 grid1(FF / BN, CAP / BM, EE);   // 32 x 2 x 8 = 512 CTAs, one launch
    dim3 grid2(DD / BN, CAP / BM, EE);   //  8 x 2 x 8 = 128 CTAs, one launch
    gemm1_kernel<<<grid1, 256, SMEM_TOT>>>(x, w1, b1);
    gemm2_kernel<<<grid2, 256, SMEM_TOT>>>(w2, b2, out);
}

// round 17
// speedup vs baseline: 4.3782x; 1.0370x over previous
#include <cuda_runtime.h>
#include <cuda_bf16.h>
#include <math.h>
#include <stdlib.h>
#include <stdint.h>

// Problem constants
#define BB 4
#define SS 2048
#define DD 1024
#define FF 4096
#define EE 8
#define TT (BB*SS)          // 8192 tokens
#define CAP 320             // int(2048/8 * 1.25)

// ---------------- scratch (~42 MB; no allocations allowed) ----------------
__device__ float g_h[EE * CAP * FF];    // hidden activations [E, CAP, F]
__device__ int   g_eidx[TT];
__device__ int   g_slot[TT];
__device__ int   g_order[EE * CAP];
__device__ int   g_cnt[EE];
__device__ float g_gsum[EE];

// ---------------- zero out + per-replay accumulators ----------------
__global__ void zero_out_kernel(float* __restrict__ out) {
    size_t i = (size_t)blockIdx.x * 256 + threadIdx.x;
    ((float4*)out)[i] = make_float4(0.f, 0.f, 0.f, 0.f);
    if (blockIdx.x == 0 && threadIdx.x < EE) g_gsum[threadIdx.x] = 0.0f;
}

// ---------------- router ----------------
__global__ void router_kernel(const float* __restrict__ x,
                              const float* __restrict__ wr) {
    __shared__ float sg[EE];
    int tid  = threadIdx.x;
    int warp = tid >> 5;
    int lane = tid & 31;
    if (tid < EE) sg[tid] = 0.0f;
    __syncthreads();

    int t = blockIdx.x * 8 + warp;
    const float* xr = x + (size_t)t * DD;

    float p0=0.f,p1=0.f,p2=0.f,p3=0.f,p4=0.f,p5=0.f,p6=0.f,p7=0.f;
    for (int k = lane; k < DD; k += 32) {
        float xv = xr[k];
        const float4* w4 = (const float4*)(wr + (size_t)k * EE);
        float4 w0 = w4[0], w1 = w4[1];
        p0 = fmaf(xv, w0.x, p0); p1 = fmaf(xv, w0.y, p1);
        p2 = fmaf(xv, w0.z, p2); p3 = fmaf(xv, w0.w, p3);
        p4 = fmaf(xv, w1.x, p4); p5 = fmaf(xv, w1.y, p5);
        p6 = fmaf(xv, w1.z, p6); p7 = fmaf(xv, w1.w, p7);
    }
#pragma unroll
    for (int off = 16; off > 0; off >>= 1) {
        p0 += __shfl_xor_sync(0xFFFFFFFFu, p0, off);
        p1 += __shfl_xor_sync(0xFFFFFFFFu, p1, off);
        p2 += __shfl_xor_sync(0xFFFFFFFFu, p2, off);
        p3 += __shfl_xor_sync(0xFFFFFFFFu, p3, off);
        p4 += __shfl_xor_sync(0xFFFFFFFFu, p4, off);
        p5 += __shfl_xor_sync(0xFFFFFFFFu, p5, off);
        p6 += __shfl_xor_sync(0xFFFFFFFFu, p6, off);
        p7 += __shfl_xor_sync(0xFFFFFFFFu, p7, off);
    }

    if (lane == 0) {
        int best = 0; float bv = p0;
        if (p1 > bv) { bv = p1; best = 1; }
        if (p2 > bv) { bv = p2; best = 2; }
        if (p3 > bv) { bv = p3; best = 3; }
        if (p4 > bv) { bv = p4; best = 4; }
        if (p5 > bv) { bv = p5; best = 5; }
        if (p6 > bv) { bv = p6; best = 6; }
        if (p7 > bv) { bv = p7; best = 7; }
        g_eidx[t] = best;
        float m = bv;
        float e0 = __expf(p0 - m), e1 = __expf(p1 - m), e2 = __expf(p2 - m), e3 = __expf(p3 - m);
        float e4 = __expf(p4 - m), e5 = __expf(p5 - m), e6 = __expf(p6 - m), e7 = __expf(p7 - m);
        float inv = 1.0f / (e0+e1+e2+e3+e4+e5+e6+e7);
        atomicAdd(&sg[0], e0 * inv); atomicAdd(&sg[1], e1 * inv);
        atomicAdd(&sg[2], e2 * inv); atomicAdd(&sg[3], e3 * inv);
        atomicAdd(&sg[4], e4 * inv); atomicAdd(&sg[5], e5 * inv);
        atomicAdd(&sg[6], e6 * inv); atomicAdd(&sg[7], e7 * inv);
    }
    __syncthreads();
    if (tid < EE) atomicAdd(&g_gsum[tid], sg[tid]);
}

// ---------------- scan ----------------
__global__ void scan_kernel(float* __restrict__ d_out, int out_size) {
    __shared__ int wtot[32][EE];
    __shared__ int totals[EE];
    __shared__ int sbase[1024][EE];

    int tid  = threadIdx.x;
    int warp = tid >> 5;
    int lane = tid & 31;
    int base = tid * 8;

    int el0 = g_eidx[base+0], el1 = g_eidx[base+1], el2 = g_eidx[base+2], el3 = g_eidx[base+3];
    int el4 = g_eidx[base+4], el5 = g_eidx[base+5], el6 = g_eidx[base+6], el7 = g_eidx[base+7];

    int q1 = (el0==el1);
    int q2 = (el0==el2)+(el1==el2);
    int q3 = (el0==el3)+(el1==el3)+(el2==el3);
    int q4 = (el0==el4)+(el1==el4)+(el2==el4)+(el3==el4);
    int q5 = (el0==el5)+(el1==el5)+(el2==el5)+(el3==el5)+(el4==el5);
    int q6 = (el0==el6)+(el1==el6)+(el2==el6)+(el3==el6)+(el4==el6)+(el5==el6);
    int q7 = (el0==el7)+(el1==el7)+(el2==el7)+(el3==el7)+(el4==el7)+(el5==el7)+(el6==el7);

#pragma unroll
    for (int e = 0; e < EE; e++) {
        int cnt = (el0==e)+(el1==e)+(el2==e)+(el3==e)+(el4==e)+(el5==e)+(el6==e)+(el7==e);
        int s = cnt;
#pragma unroll
        for (int off = 1; off < 32; off <<= 1) {
            int o = __shfl_up_sync(0xFFFFFFFFu, s, off);
            if (lane >= off) s += o;
        }
        sbase[tid][e] = s - cnt;
        if (lane == 31) wtot[warp][e] = s;
    }
    __syncthreads();

    if (warp == 0) {
#pragma unroll
        for (int e = 0; e < EE; e++) {
            int v = wtot[lane][e], s = v;
#pragma unroll
            for (int off = 1; off < 32; off <<= 1) {
                int o = __shfl_up_sync(0xFFFFFFFFu, s, off);
                if (lane >= off) s += o;
            }
            wtot[lane][e] = s - v;
            if (lane == 31) totals[e] = s;
        }
    }
    __syncthreads();

#pragma unroll
    for (int e = 0; e < EE; e++) sbase[tid][e] += wtot[warp][e];
    __syncthreads();

    {
        int g0 = sbase[tid][el0];
        int g1 = sbase[tid][el1] + q1;
        int g2 = sbase[tid][el2] + q2;
        int g3 = sbase[tid][el3] + q3;
        int g4 = sbase[tid][el4] + q4;
        int g5 = sbase[tid][el5] + q5;
        int g6 = sbase[tid][el6] + q6;
        int g7 = sbase[tid][el7] + q7;
        g_slot[base+0] = (g0 < CAP) ? g0 : -1;
        g_slot[base+1] = (g1 < CAP) ? g1 : -1;
        g_slot[base+2] = (g2 < CAP) ? g2 : -1;
        g_slot[base+3] = (g3 < CAP) ? g3 : -1;
        g_slot[base+4] = (g4 < CAP) ? g4 : -1;
        g_slot[base+5] = (g5 < CAP) ? g5 : -1;
        g_slot[base+6] = (g6 < CAP) ? g6 : -1;
        g_slot[base+7] = (g7 < CAP) ? g7 : -1;
        if (g0 < CAP) g_order[el0*CAP + g0] = base+0;
        if (g1 < CAP) g_order[el1*CAP + g1] = base+1;
        if (g2 < CAP) g_order[el2*CAP + g2] = base+2;
        if (g3 < CAP) g_order[el3*CAP + g3] = base+3;
        if (g4 < CAP) g_order[el4*CAP + g4] = base+4;
        if (g5 < CAP) g_order[el5*CAP + g5] = base+5;
        if (g6 < CAP) g_order[el6*CAP + g6] = base+6;
        if (g7 < CAP) g_order[el7*CAP + g7] = base+7;
    }

    if (tid < EE) {
        int c = totals[tid];
        g_cnt[tid] = (c < CAP) ? c : CAP;
    }

    if (tid == 0 && out_size > TT * DD) {
        float loss = 0.0f;
        float invT = 1.0f / (float)TT;
#pragma unroll
        for (int e = 0; e < EE; e++)
            loss += ((float)totals[e] * invT) * (g_gsum[e] * invT);
        d_out[TT * DD] = (float)EE * loss;
    }
}

// ======== tf32 mma.sync GEMMs: BM=160, 3-stage cp.async, 2 CTAs/SM ========
#define BM 160
#define MF 5                 // m-fragments per warp (80/16)
#define BN 128
#define BK 16
#define STAGES 3
#define AS_LD (BK + 4)       // 20 floats
#define BS_LD (BN + 8)       // 136 floats
#define A_SLOTS (BM * 4)     // 640 float4 slots per A stage

// dynamic smem layout (bytes): total exactly 64 KB -> 2 CTAs/SM
#define SM_SROW   0
#define SM_A      1024
#define A_BUF_B   (BM * AS_LD * 4)          // 12800
#define SM_B      (SM_A + STAGES * A_BUF_B) // 1024 + 38400 = 39424
#define B_BUF_B   (BK * BS_LD * 4)          // 8704
#define SMEM_TOT  (SM_B + STAGES * B_BUF_B) // 39424 + 26112 = 65536

__device__ __forceinline__ unsigned f2tf(float f) {
    unsigned r;
    asm("cvt.rna.tf32.f32 %0, %1;" : "=r"(r) : "f"(f));
    return r;
}

__device__ __forceinline__ void cpa16(unsigned dst, const float* src) {
    asm volatile("cp.async.ca.shared.global [%0], [%1], 16;" :: "r"(dst), "l"(src));
}
__device__ __forceinline__ void cpa16z(unsigned dst, const float* src) {
    asm volatile("cp.async.ca.shared.global [%0], [%1], 16, 0;" :: "r"(dst), "l"(src));
}
#define CP_COMMIT() asm volatile("cp.async.commit_group;")
#define CP_WAIT1()  asm volatile("cp.async.wait_group 1;")

#define MMA_TF32(d, av, bv) \
    asm volatile("mma.sync.aligned.m16n8k8.row.col.f32.tf32.tf32.f32 " \
                 "{%0,%1,%2,%3}, {%4,%5,%6,%7}, {%8,%9}, {%0,%1,%2,%3};" \
                 : "+f"(d[0]), "+f"(d[1]), "+f"(d[2]), "+f"(d[3]) \
                 : "r"(av[0]), "r"(av[1]), "r"(av[2]), "r"(av[3]), \
                   "r"(bv[0]), "r"(bv[1]))

__device__ __forceinline__ void tc_compute(const float (*Asb)[AS_LD],
                                           const float (*Bsb)[BS_LD],
                                           float (*acc)[4][4],
                                           int mwb, int nwb, int gid, int tg) {
#pragma unroll
    for (int ks = 0; ks < 2; ks++) {
        int k8 = ks * 8;
        unsigned af[MF][4];
#pragma unroll
        for (int mi = 0; mi < MF; mi++) {
            int r0 = mwb + mi * 16 + gid;
            af[mi][0] = f2tf(Asb[r0    ][k8 + tg    ]);
            af[mi][1] = f2tf(Asb[r0 + 8][k8 + tg    ]);
            af[mi][2] = f2tf(Asb[r0    ][k8 + tg + 4]);
            af[mi][3] = f2tf(Asb[r0 + 8][k8 + tg + 4]);
        }
        unsigned bf[4][2];
#pragma unroll
        for (int ni = 0; ni < 4; ni++) {
            int c0 = nwb + ni * 8 + gid;
            bf[ni][0] = f2tf(Bsb[k8 + tg    ][c0]);
            bf[ni][1] = f2tf(Bsb[k8 + tg + 4][c0]);
        }
#pragma unroll
        for (int mi = 0; mi < MF; mi++)
#pragma unroll
            for (int ni = 0; ni < 4; ni++)
                MMA_TF32(acc[mi][ni], af[mi], bf[ni]);
    }
}

// ---------------- GEMM1: h = relu(gather(x) @ w1 + b1)   [single launch, all F] ----
__global__ __launch_bounds__(256, 2)
void gemm1_kernel(const float* __restrict__ x, const float* __restrict__ w1,
                  const float* __restrict__ b1) {
    extern __shared__ char smem[];
    int e  = blockIdx.z;
    int m0 = blockIdx.y * BM;
    int n0 = blockIdx.x * BN;
    const float* Bp   = w1 + (size_t)e * DD * FF;        // row k stride FF
    const float* bias = b1 + (size_t)e * FF;
    float* C = g_h + (size_t)e * CAP * FF;
    int cnt = g_cnt[e];

    int* srow = (int*)(smem + SM_SROW);
    int tid = threadIdx.x;
    if (tid < BM) {
        int m = m0 + tid;
        srow[tid] = (m < cnt) ? g_order[e * CAP + m] : -1;
    }
    __syncthreads();

    int wid = tid >> 5, lane = tid & 31;
    int gid = lane >> 2, tg = lane & 3;
    int mwb = (wid >> 2) * 80;
    int nwb = (wid & 3) * 32;

    int bk = tid >> 4;
    int bc = (tid & 15) * 8;
    const float* brow = Bp + (size_t)bk * FF + n0 + bc;

    unsigned aBase = (unsigned)__cvta_generic_to_shared(smem + SM_A);
    unsigned bBase = (unsigned)__cvta_generic_to_shared(smem + SM_B);
    unsigned bOff  = ((unsigned)(bk * BS_LD + bc)) * 4u;

    float acc[MF][4][4];
#pragma unroll
    for (int mi = 0; mi < MF; mi++)
#pragma unroll
        for (int ni = 0; ni < 4; ni++)
#pragma unroll
            for (int i = 0; i < 4; i++) acc[mi][ni][i] = 0.0f;

    const int nit = DD / BK;   // 64
#pragma unroll
    for (int s = 0; s < STAGES - 1; s++) {
        int k0 = s * BK;
        unsigned aSt = aBase + (unsigned)s * A_BUF_B;
        for (int slot = tid; slot < A_SLOTS; slot += 256) {
            int row = slot >> 2, kq = (slot & 3) * 4;
            unsigned ad = aSt + ((unsigned)(row * AS_LD + kq)) * 4u;
            int gt = srow[row];
            if (gt >= 0) cpa16(ad, x + (size_t)gt * DD + k0 + kq);
            else         cpa16z(ad, x);
        }
        unsigned bd = bBase + (unsigned)s * B_BUF_B + bOff;
        const float* bs = brow + (size_t)k0 * FF;
        cpa16(bd, bs); cpa16(bd + 16, bs + 4);
        CP_COMMIT();
    }

    int sIdx = 0, pIdx = STAGES - 1;   // compute index, prefetch stage index
    for (int t = 0; t < nit; t++) {
        CP_WAIT1();
        __syncthreads();
        int pf = t + STAGES - 1;
        if (pf < nit) {
            int k0 = pf * BK;
            unsigned aSt = aBase + (unsigned)pIdx * A_BUF_B;
            for (int slot = tid; slot < A_SLOTS; slot += 256) {
                int row = slot >> 2, kq = (slot & 3) * 4;
                unsigned ad = aSt + ((unsigned)(row * AS_LD + kq)) * 4u;
                int gt = srow[row];
                if (gt >= 0) cpa16(ad, x + (size_t)gt * DD + k0 + kq);
                else         cpa16z(ad, x);
            }
            unsigned bd = bBase + (unsigned)pIdx * B_BUF_B + bOff;
            const float* bs = brow + (size_t)k0 * FF;
            cpa16(bd, bs); cpa16(bd + 16, bs + 4);
        }
        CP_COMMIT();   // every iter -> wait_group 1 always certifies tile t
        tc_compute((const float(*)[AS_LD])(smem + SM_A + sIdx * A_BUF_B),
                   (const float(*)[BS_LD])(smem + SM_B + sIdx * B_BUF_B),
                   acc, mwb, nwb, gid, tg);
        sIdx = (sIdx + 1 == STAGES) ? 0 : sIdx + 1;
        pIdx = (pIdx + 1 == STAGES) ? 0 : pIdx + 1;
    }

    // epilogue: + bias, relu -> g_h (rows always < CAP since 2*BM == CAP)
#pragma unroll
    for (int mi = 0; mi < MF; mi++) {
#pragma unroll
        for (int i = 0; i < 2; i++) {
            int row = m0 + mwb + mi * 16 + gid + i * 8;
#pragma unroll
            for (int ni = 0; ni < 4; ni++) {
                int col = n0 + nwb + ni * 8 + tg * 2;
                float2 o;
                o.x = fmaxf(acc[mi][ni][i*2+0] + bias[col],     0.0f);
                o.y = fmaxf(acc[mi][ni][i*2+1] + bias[col + 1], 0.0f);
                *(float2*)(C + (size_t)row * FF + col) = o;
            }
        }
    }
}

// ---------------- GEMM2: out[token] = h @ w2 + b2   [single launch, K=4096] ----
__global__ __launch_bounds__(256, 2)
void gemm2_kernel(const float* __restrict__ w2, const float* __restrict__ b2,
                  float* __restrict__ out) {
    extern __shared__ char smem[];
    int e  = blockIdx.z;
    int m0 = blockIdx.y * BM;
    int n0 = blockIdx.x * BN;
    const float* Ap   = g_h + (size_t)e * CAP * FF;
    const float* Bp   = w2 + (size_t)e * FF * DD;
    const float* bias = b2 + (size_t)e * DD;
    int cnt = g_cnt[e];

    int* srow = (int*)(smem + SM_SROW);
    int tid = threadIdx.x;
    if (tid < BM) {
        int m = m0 + tid;
        srow[tid] = (m < cnt) ? g_order[e * CAP + m] : -1;
    }
    __syncthreads();

    int wid = tid >> 5, lane = tid & 31;
    int gid = lane >> 2, tg = lane & 3;
    int mwb = (wid >> 2) * 80;
    int nwb = (wid & 3) * 32;

    int bk = tid >> 4;
    int bc = (tid & 15) * 8;
    const float* brow  = Bp + (size_t)bk * DD + n0 + bc;
    const float* Arow0 = Ap + (size_t)m0 * FF;     // rows m0..m0+159 all < CAP

    unsigned aBase = (unsigned)__cvta_generic_to_shared(smem + SM_A);
    unsigned bBase = (unsigned)__cvta_generic_to_shared(smem + SM_B);
    unsigned bOff  = ((unsigned)(bk * BS_LD + bc)) * 4u;

    float acc[MF][4][4];
#pragma unroll
    for (int mi = 0; mi < MF; mi++)
#pragma unroll
        for (int ni = 0; ni < 4; ni++)
#pragma unroll
            for (int i = 0; i < 4; i++) acc[mi][ni][i] = 0.0f;

    const int nit = FF / BK;   // 256
#pragma unroll
    for (int s = 0; s < STAGES - 1; s++) {
        int k0 = s * BK;
        unsigned aSt = aBase + (unsigned)s * A_BUF_B;
        for (int slot = tid; slot < A_SLOTS; slot += 256) {
            int row = slot >> 2, kq = (slot & 3) * 4;
            unsigned ad = aSt + ((unsigned)(row * AS_LD + kq)) * 4u;
            cpa16(ad, Arow0 + (size_t)row * FF + k0 + kq);
        }
        unsigned bd = bBase + (unsigned)s * B_BUF_B + bOff;
        const float* bs = brow + (size_t)k0 * DD;
        cpa16(bd, bs); cpa16(bd + 16, bs + 4);
        CP_COMMIT();
    }

    int sIdx = 0, pIdx = STAGES - 1;
    for (int t = 0; t < nit; t++) {
        CP_WAIT1();
        __syncthreads();
        int pf = t + STAGES - 1;
        if (pf < nit) {
            int k0 = pf * BK;
            unsigned aSt = aBase + (unsigned)pIdx * A_BUF_B;
            for (int slot = tid; slot < A_SLOTS; slot += 256) {
                int row = slot >> 2, kq = (slot & 3) * 4;
                unsigned ad = aSt + ((unsigned)(row * AS_LD + kq)) * 4u;
                cpa16(ad, Arow0 + (size_t)row * FF + k0 + kq);
            }
            unsigned bd = bBase + (unsigned)pIdx * B_BUF_B + bOff;
            const float* bs = brow + (size_t)k0 * DD;
            cpa16(bd, bs); cpa16(bd + 16, bs + 4);
        }
        CP_COMMIT();
        tc_compute((const float(*)[AS_LD])(smem + SM_A + sIdx * A_BUF_B),
                   (const float(*)[BS_LD])(smem + SM_B + sIdx * B_BUF_B),
                   acc, mwb, nwb, gid, tg);
        sIdx = (sIdx + 1 == STAGES) ? 0 : sIdx + 1;
        pIdx = (pIdx + 1 == STAGES) ? 0 : pIdx + 1;
    }

    // epilogue: scatter to out with bias (single pass over K, no RMW)
#pragma unroll
    for (int mi = 0; mi < MF; mi++) {
#pragma unroll
        for (int i = 0; i < 2; i++) {
            int lr = mwb + mi * 16 + gid + i * 8;
            int t  = srow[lr];
            if (t >= 0) {
#pragma unroll
                for (int ni = 0; ni < 4; ni++) {
                    int col = n0 + nwb + ni * 8 + tg * 2;
                    float2 o;
                    o.x = acc[mi][ni][i*2+0] + bias[col];
                    o.y = acc[mi][ni][i*2+1] + bias[col + 1];
                    *(float2*)(out + (size_t)t * DD + col) = o;
                }
            }
        }
    }
}

// ---------------- eager-load + smem attr (default-priority ctor) ----------------
namespace {
struct ModulePreloader {
    ModulePreloader() {
        setenv("CUDA_MODULE_LOADING", "EAGER", 1);
        void* p = nullptr;
        (void)cudaGetSymbolAddress(&p, g_h);
        (void)cudaGetSymbolAddress(&p, g_eidx);
        (void)cudaGetSymbolAddress(&p, g_slot);
        (void)cudaGetSymbolAddress(&p, g_order);
        (void)cudaGetSymbolAddress(&p, g_cnt);
        (void)cudaGetSymbolAddress(&p, g_gsum);
        cudaFuncAttributes a;
        (void)cudaFuncGetAttributes(&a, (const void*)router_kernel);
        (void)cudaFuncGetAttributes(&a, (const void*)scan_kernel);
        (void)cudaFuncGetAttributes(&a, (const void*)gemm1_kernel);
        (void)cudaFuncGetAttributes(&a, (const void*)gemm2_kernel);
        (void)cudaFuncGetAttributes(&a, (const void*)zero_out_kernel);
        (void)cudaFuncSetAttribute((const void*)gemm1_kernel,
                                   cudaFuncAttributeMaxDynamicSharedMemorySize, SMEM_TOT);
        (void)cudaFuncSetAttribute((const void*)gemm2_kernel,
                                   cudaFuncAttributeMaxDynamicSharedMemorySize, SMEM_TOT);
    }
};
ModulePreloader g_module_preloader;
}

// ---------------- launch ----------------
extern "C" void kernel_launch(void* const* d_in, const int* in_sizes, int n_in,
                              void* d_out, int out_size) {
    const float* x   = (const float*)d_in[0];
    const float* wr  = (const float*)d_in[1];
    const float* w1  = (const float*)d_in[2];
    const float* b1  = (const float*)d_in[3];
    const float* w2  = (const float*)d_in[4];
    const float* b2  = (const float*)d_in[5];
    float* out = (float*)d_out;

    (void)cudaFuncSetAttribute((const void*)gemm1_kernel,
                               cudaFuncAttributeMaxDynamicSharedMemorySize, SMEM_TOT);
    (void)cudaFuncSetAttribute((const void*)gemm2_kernel,
                               cudaFuncAttributeMaxDynamicSharedMemorySize, SMEM_TOT);

    zero_out_kernel<<<(TT * DD / 4) / 256, 256>>>(out);   // also zeroes g_gsum
    router_kernel<<<TT / 8, 256>>>(x, wr);
    scan_kernel<<<1, 1024>>>(out, out_size);

    dim3 grid1(FF / BN, CAP / BM, EE);   // 32 x 2 x 8 = 512 CTAs, one launch
    dim3 grid2(DD / BN, CAP / BM, EE);   //  8 x 2 x 8 = 128 CTAs, one launch
    gemm1_kernel<<<grid1, 256, SMEM_TOT>>>(x, w1, b1);
    gemm2_kernel<<<grid2, 256, SMEM_TOT>>>(w2, b2, out);
}